// round 12
// baseline (speedup 1.0000x reference)
#include <cuda_runtime.h>
#include <cuda_fp16.h>
#include <cstdint>

#define EPS 1e-6f
// B=8, S=4096, IN=1024, HD=1024, OUT=1024, M=32768

// ---------------- scratch (allocation-free device globals) ----------------
__device__ __half g_xh [33554432];  // fp16 x            [32768,1024] (64MB)
__device__ __half g_wqT[1048576];   // [N,K] transposed fp16
__device__ __half g_wkT[1048576];
__device__ __half g_wvT[1048576];
__device__ __half g_woT[1048576];
__device__ __half g_att[33554432];  // attn scratch fp16 (64MB)
__device__ float  g_KV[8192];       // [B, H*D]
__device__ float  g_KS[8192];

// ---------------- helpers ----------------
__device__ __forceinline__ uint32_t sptr(const void* p) {
    return (uint32_t)__cvta_generic_to_shared(p);
}
__device__ __forceinline__ void cpa16(uint32_t d, const void* s) {
    asm volatile("cp.async.cg.shared.global [%0], [%1], 16;\n" :: "r"(d), "l"(s));
}
__device__ __forceinline__ void cp_commit() { asm volatile("cp.async.commit_group;\n"); }
template<int N> __device__ __forceinline__ void cp_wait() {
    asm volatile("cp.async.wait_group %0;\n" :: "n"(N));
}
__device__ __forceinline__ void ldsm4(uint32_t& r0, uint32_t& r1, uint32_t& r2, uint32_t& r3,
                                      uint32_t a) {
    asm volatile("ldmatrix.sync.aligned.m8n8.x4.shared.b16 {%0,%1,%2,%3}, [%4];"
                 : "=r"(r0), "=r"(r1), "=r"(r2), "=r"(r3) : "r"(a));
}
__device__ __forceinline__ void mma16(float* c, const uint32_t* a, const uint32_t* b) {
    asm volatile(
        "mma.sync.aligned.m16n8k16.row.col.f32.f16.f16.f32 "
        "{%0,%1,%2,%3}, {%4,%5,%6,%7}, {%8,%9}, {%0,%1,%2,%3};"
        : "+f"(c[0]), "+f"(c[1]), "+f"(c[2]), "+f"(c[3])
        : "r"(a[0]), "r"(a[1]), "r"(a[2]), "r"(a[3]), "r"(b[0]), "r"(b[1]));
}
__device__ __forceinline__ float fmap(float x) {   // elu(x)+1
    return x > 0.f ? x + 1.f : __expf(x);
}
// tanh-approx gelu via sigmoid identity: gelu(x) = x - x/(exp(2z)+1),
// z = 0.7978845608*(x + 0.044715 x^3). Same math as tanhf version, ~1e-6 acc,
// ~8 instrs (2 MUFU) vs tanhf's branchy ~25.
__device__ __forceinline__ float gelu_t(float x) {
    float z2 = 1.5957691216057308f * (x + 0.044715f * x * x * x);
    float e  = __expf(z2);
    return x - x * __fdividef(1.f, e + 1.f);
}

// ---------------- prep kernels ----------------
__global__ void k_tohalf(const float4* __restrict__ src, __half2* __restrict__ dst, int n4) {
    int i = blockIdx.x * blockDim.x + threadIdx.x;
    if (i < n4) {
        float4 v = src[i];
        dst[2 * i]     = __floats2half2_rn(v.x, v.y);
        dst[2 * i + 1] = __floats2half2_rn(v.z, v.w);
    }
}
// transpose 1024x1024 [K][N] -> [N][K], convert to fp16; blockIdx.z picks matrix
__global__ void k_wt(const float* __restrict__ s0, __half* __restrict__ d0,
                     const float* __restrict__ s1, __half* __restrict__ d1,
                     const float* __restrict__ s2, __half* __restrict__ d2,
                     const float* __restrict__ s3, __half* __restrict__ d3)
{
    __shared__ float t[32][33];
    const float* src; __half* dst;
    switch (blockIdx.z) {
        case 0:  src = s0; dst = d0; break;
        case 1:  src = s1; dst = d1; break;
        case 2:  src = s2; dst = d2; break;
        default: src = s3; dst = d3; break;
    }
    int bx = blockIdx.x << 5, by = blockIdx.y << 5;
    int tx = threadIdx.x, ty = threadIdx.y;   // 32 x 8
#pragma unroll
    for (int i = 0; i < 4; i++)
        t[ty + i * 8][tx] = src[(size_t)(by + ty + i * 8) * 1024 + bx + tx];
    __syncthreads();
#pragma unroll
    for (int i = 0; i < 4; i++)
        dst[(size_t)(bx + ty + i * 8) * 1024 + by + tx] = __float2half_rn(t[tx][ty + i * 8]);
}
__global__ void k_zero(float* a, float* b, int n) {
    int i = blockIdx.x * blockDim.x + threadIdx.x;
    if (i < n) { a[i] = 0.f; b[i] = 0.f; }
}

// swizzled smem byte address of 16B chunk (r row of 128B, c chunk 0..7)
#define SWC(base, r, c) ((base) + (r) * 128 + (((c) ^ ((r) & 7)) << 4))

// ---------------- Kernel 1: K/V dual-GEMM + KV/Ksum reduction ----------------
// BM=128, BN=64, BK=64, 256 thr, warps 4(m)x2(n), warp tile 32x32
// smem/stage: A 16K + Bk 8K + Bv 8K = 32K; 3 stages = 96K; 2 CTA/SM
__global__ void __launch_bounds__(256) k_kv(
    const __half* __restrict__ X, const __half* __restrict__ WkT, const __half* __restrict__ WvT,
    const float* __restrict__ BK, const float* __restrict__ BV,
    float* __restrict__ KV, float* __restrict__ KS)
{
    extern __shared__ char sm[];
    const uint32_t smb = sptr(sm);
    const int tid = threadIdx.x, lane = tid & 31, wid = tid >> 5;
    const int wm = wid >> 1, wn = wid & 1;
    const int rowBase = blockIdx.y << 7;
    const int colBase = blockIdx.x << 6;

    float accK[2][4][4], accV[2][4][4];
#pragma unroll
    for (int i = 0; i < 2; i++)
#pragma unroll
        for (int j = 0; j < 4; j++)
#pragma unroll
            for (int c = 0; c < 4; c++) { accK[i][j][c] = 0.f; accV[i][j][c] = 0.f; }

    auto load_chunk = [&](int kt, int s) {
        const uint32_t sa  = smb + s * 32768;
        const uint32_t sbk = sa + 16384;
        const uint32_t sbv = sbk + 8192;
        const __half* gA = X   + (size_t)rowBase * 1024 + kt * 64;
        const __half* gK = WkT + (size_t)colBase * 1024 + kt * 64;
        const __half* gV = WvT + (size_t)colBase * 1024 + kt * 64;
#pragma unroll
        for (int l = 0; l < 4; l++) {
            int e = l * 256 + tid, r = e >> 3, c = e & 7;
            cpa16(SWC(sa, r, c), gA + (size_t)r * 1024 + c * 8);
        }
#pragma unroll
        for (int l = 0; l < 2; l++) {
            int e = l * 256 + tid, r = e >> 3, c = e & 7;
            cpa16(SWC(sbk, r, c), gK + (size_t)r * 1024 + c * 8);
            cpa16(SWC(sbv, r, c), gV + (size_t)r * 1024 + c * 8);
        }
        cp_commit();
    };

    load_chunk(0, 0);
    load_chunk(1, 1);

    // ldmatrix lane roles
    const int rA0 = wm * 32 + (lane & 15);        // + mi*16
    const int selA = lane >> 4;                   // chunk +0/+1
    const int cB0 = wn * 32 + (lane & 7) + ((lane >> 4) << 3);  // + pair*16
    const int selB = (lane >> 3) & 1;

    for (int kt = 0; kt < 16; kt++) {
        if (kt < 15) cp_wait<1>(); else cp_wait<0>();
        __syncthreads();
        const int s = kt % 3;
        const uint32_t sa  = smb + s * 32768;
        const uint32_t sbk = sa + 16384;
        const uint32_t sbv = sbk + 8192;
#pragma unroll
        for (int ks = 0; ks < 4; ks++) {
            uint32_t af[2][4], bk2[4][2], bv2[4][2];
#pragma unroll
            for (int mi = 0; mi < 2; mi++) {
                const int r = rA0 + mi * 16;
                ldsm4(af[mi][0], af[mi][1], af[mi][2], af[mi][3],
                      sa + r * 128 + (((2 * ks + selA) ^ (r & 7)) << 4));
            }
#pragma unroll
            for (int p = 0; p < 2; p++) {
                const int c = cB0 + p * 16;
                const uint32_t off = c * 128 + (((2 * ks + selB) ^ (c & 7)) << 4);
                ldsm4(bk2[2 * p][0], bk2[2 * p][1], bk2[2 * p + 1][0], bk2[2 * p + 1][1],
                      sbk + off);
                ldsm4(bv2[2 * p][0], bv2[2 * p][1], bv2[2 * p + 1][0], bv2[2 * p + 1][1],
                      sbv + off);
            }
            // overlap next-chunk cp.async issue with ks=0 LDSM latency
            if (ks == 0 && kt < 14) load_chunk(kt + 2, (kt + 2) % 3);
#pragma unroll
            for (int mi = 0; mi < 2; mi++)
#pragma unroll
                for (int ni = 0; ni < 4; ni++) {
                    mma16(accK[mi][ni], af[mi], bk2[ni]);
                    mma16(accV[mi][ni], af[mi], bv2[ni]);
                }
        }
    }

    // epilogue: K = elu+1, reduce K*v and K over the 128 s-rows of this block
    const int b = rowBase >> 12;
#pragma unroll
    for (int ni = 0; ni < 4; ni++) {
#pragma unroll
        for (int c = 0; c < 2; c++) {
            const int colg = colBase + wn * 32 + ni * 8 + 2 * (lane & 3) + c;
            const float bkc = BK[colg], bvc = BV[colg];
            float skv = 0.f, sk = 0.f;
#pragma unroll
            for (int mi = 0; mi < 2; mi++) {
                float kA = accK[mi][ni][c]     + bkc;
                float kB = accK[mi][ni][c + 2] + bkc;
                float vA = accV[mi][ni][c]     + bvc;
                float vB = accV[mi][ni][c + 2] + bvc;
                float KA = fmap(kA), KB = fmap(kB);
                skv += KA * vA + KB * vB;
                sk  += KA + KB;
            }
#pragma unroll
            for (int off = 16; off >= 4; off >>= 1) {
                skv += __shfl_xor_sync(0xffffffffu, skv, off);
                sk  += __shfl_xor_sync(0xffffffffu, sk,  off);
            }
            if (lane < 4) {
                atomicAdd(&KV[b * 1024 + colg], skv);
                atomicAdd(&KS[b * 1024 + colg], sk);
            }
        }
    }
}

// ---------------- Kernels 2/3 common mainloop ----------------
// BM=128, BN=128, BK=64, 256 thr, warps 2(m)x4(n), warp tile 64x32
// smem/stage: A 16K + B 16K = 32K; 3 stages = 96K; 2 CTA/SM
#define GEMM_MAIN(WT)                                                                   \
    extern __shared__ char sm[];                                                        \
    const uint32_t smb = sptr(sm);                                                      \
    const int tid = threadIdx.x, lane = tid & 31, wid = tid >> 5;                       \
    const int wm = wid >> 2, wn = wid & 3;                                              \
    const int rowBase = blockIdx.y << 7;                                                \
    const int colBase = blockIdx.x << 7;                                                \
    float acc[4][4][4];                                                                 \
    _Pragma("unroll") for (int i = 0; i < 4; i++)                                       \
    _Pragma("unroll") for (int j = 0; j < 4; j++)                                       \
    _Pragma("unroll") for (int c = 0; c < 4; c++) acc[i][j][c] = 0.f;                   \
    auto load_chunk = [&](int kt, int s) {                                              \
        const uint32_t sa = smb + s * 32768;                                            \
        const uint32_t sb = sa + 16384;                                                 \
        const __half* gA = A  + (size_t)rowBase * 1024 + kt * 64;                       \
        const __half* gB = WT + (size_t)colBase * 1024 + kt * 64;                       \
        _Pragma("unroll") for (int l = 0; l < 4; l++) {                                 \
            int e = l * 256 + tid, r = e >> 3, c = e & 7;                               \
            cpa16(SWC(sa, r, c), gA + (size_t)r * 1024 + c * 8);                        \
            cpa16(SWC(sb, r, c), gB + (size_t)r * 1024 + c * 8);                        \
        }                                                                               \
        cp_commit();                                                                    \
    };                                                                                  \
    load_chunk(0, 0);                                                                   \
    load_chunk(1, 1);                                                                   \
    const int rA0 = wm * 64 + (lane & 15);                                              \
    const int selA = lane >> 4;                                                         \
    const int cB0 = wn * 32 + (lane & 7) + ((lane >> 4) << 3);                          \
    const int selB = (lane >> 3) & 1;                                                   \
    for (int kt = 0; kt < 16; kt++) {                                                   \
        if (kt < 15) cp_wait<1>(); else cp_wait<0>();                                   \
        __syncthreads();                                                                \
        const int s = kt % 3;                                                           \
        const uint32_t sa = smb + s * 32768;                                            \
        const uint32_t sb = sa + 16384;                                                 \
        _Pragma("unroll") for (int ks = 0; ks < 4; ks++) {                              \
            uint32_t af[4][4], bf[4][2];                                                \
            _Pragma("unroll") for (int mi = 0; mi < 4; mi++) {                          \
                const int r = rA0 + mi * 16;                                            \
                ldsm4(af[mi][0], af[mi][1], af[mi][2], af[mi][3],                       \
                      sa + r * 128 + (((2 * ks + selA) ^ (r & 7)) << 4));               \
            }                                                                           \
            _Pragma("unroll") for (int p = 0; p < 2; p++) {                             \
                const int c = cB0 + p * 16;                                             \
                ldsm4(bf[2 * p][0], bf[2 * p][1], bf[2 * p + 1][0], bf[2 * p + 1][1],   \
                      sb + c * 128 + (((2 * ks + selB) ^ (c & 7)) << 4));               \
            }                                                                           \
            if (ks == 0 && kt < 14) load_chunk(kt + 2, (kt + 2) % 3);                   \
            _Pragma("unroll") for (int mi = 0; mi < 4; mi++)                            \
            _Pragma("unroll") for (int ni = 0; ni < 4; ni++)                            \
                mma16(acc[mi][ni], af[mi], bf[ni]);                                     \
        }                                                                               \
    }

// ---------------- Kernel 2: Q projection + attn epilogue (fp16 out) ----------------
__global__ void __launch_bounds__(256) k_q_attn(
    const __half* __restrict__ A, const __half* __restrict__ WT,
    const float* __restrict__ BQ, const float* __restrict__ KV,
    const float* __restrict__ KS, __half* __restrict__ ATT)
{
    GEMM_MAIN(WT)
    const int b = rowBase >> 12;
    const int g = lane >> 2;
#pragma unroll
    for (int mi = 0; mi < 4; mi++) {
        const int r0 = rowBase + wm * 64 + mi * 16 + g;
#pragma unroll
        for (int ni = 0; ni < 4; ni++) {
            const int c0 = colBase + wn * 32 + ni * 8 + 2 * (lane & 3);
            const float kv0 = KV[b * 1024 + c0], kv1 = KV[b * 1024 + c0 + 1];
            const float ks0 = KS[b * 1024 + c0], ks1 = KS[b * 1024 + c0 + 1];
            const float bq0 = BQ[c0], bq1 = BQ[c0 + 1];
#pragma unroll
            for (int h = 0; h < 2; h++) {
                const int r = r0 + 8 * h;
                float Q0 = fmap(acc[mi][ni][2 * h + 0] + bq0);
                float Q1 = fmap(acc[mi][ni][2 * h + 1] + bq1);
                float a0 = __fdividef(Q0 * kv0, Q0 * ks0 + EPS);
                float a1 = __fdividef(Q1 * kv1, Q1 * ks1 + EPS);
                *(__half2*)(&ATT[(size_t)r * 1024 + c0]) = __floats2half2_rn(a0, a1);
            }
        }
    }
}

// ---------------- Kernel 3: output projection + gelu (fp32 out) ----------------
__global__ void __launch_bounds__(256) k_out(
    const __half* __restrict__ A, const __half* __restrict__ WT,
    const float* __restrict__ BO, float* __restrict__ OUT)
{
    GEMM_MAIN(WT)
    const int g = lane >> 2;
#pragma unroll
    for (int mi = 0; mi < 4; mi++) {
        const int r0 = rowBase + wm * 64 + mi * 16 + g;
#pragma unroll
        for (int ni = 0; ni < 4; ni++) {
            const int c0 = colBase + wn * 32 + ni * 8 + 2 * (lane & 3);
            const float bo0 = BO[c0], bo1 = BO[c0 + 1];
#pragma unroll
            for (int h = 0; h < 2; h++) {
                const int r = r0 + 8 * h;
                float o0 = gelu_t(acc[mi][ni][2 * h + 0] + bo0);
                float o1 = gelu_t(acc[mi][ni][2 * h + 1] + bo1);
                *(float2*)(&OUT[(size_t)r * 1024 + c0]) = make_float2(o0, o1);
            }
        }
    }
}

// ---------------- host launcher ----------------
extern "C" void kernel_launch(void* const* d_in, const int* in_sizes, int n_in,
                              void* d_out, int out_size)
{
    const float* x  = (const float*)d_in[0];
    const float* wq = (const float*)d_in[1];
    const float* bq = (const float*)d_in[2];
    const float* wk = (const float*)d_in[3];
    const float* bk = (const float*)d_in[4];
    const float* wv = (const float*)d_in[5];
    const float* bv = (const float*)d_in[6];
    const float* wo = (const float*)d_in[7];
    const float* bo = (const float*)d_in[8];
    float* out = (float*)d_out;

    void *p_xh, *p_wq, *p_wk, *p_wv, *p_wo, *p_att, *p_kv, *p_ks;
    cudaGetSymbolAddress(&p_xh,  g_xh);
    cudaGetSymbolAddress(&p_wq,  g_wqT);
    cudaGetSymbolAddress(&p_wk,  g_wkT);
    cudaGetSymbolAddress(&p_wv,  g_wvT);
    cudaGetSymbolAddress(&p_wo,  g_woT);
    cudaGetSymbolAddress(&p_att, g_att);
    cudaGetSymbolAddress(&p_kv,  g_KV);
    cudaGetSymbolAddress(&p_ks,  g_KS);

    const int SMB = 98304;   // 3 stages x 32K
    cudaFuncSetAttribute(k_kv,     cudaFuncAttributeMaxDynamicSharedMemorySize, SMB);
    cudaFuncSetAttribute(k_q_attn, cudaFuncAttributeMaxDynamicSharedMemorySize, SMB);
    cudaFuncSetAttribute(k_out,    cudaFuncAttributeMaxDynamicSharedMemorySize, SMB);

    // prep: x -> fp16; transpose+convert weights to [N,K] fp16; zero accumulators
    k_tohalf<<<32768, 256>>>((const float4*)x, (__half2*)p_xh, 8388608);
    k_wt<<<dim3(32, 32, 4), dim3(32, 8)>>>(wq, (__half*)p_wq, wk, (__half*)p_wk,
                                           wv, (__half*)p_wv, wo, (__half*)p_wo);
    k_zero<<<8, 1024>>>((float*)p_kv, (float*)p_ks, 8192);

    // 1) K,V projections + KV/Ksum reduction (K,V never materialized)
    k_kv<<<dim3(16, 256), 256, SMB>>>((const __half*)p_xh,
                                      (const __half*)p_wk, (const __half*)p_wv,
                                      bk, bv, (float*)p_kv, (float*)p_ks);
    // 2) Q projection + linear-attention epilogue -> attn scratch (fp16)
    k_q_attn<<<dim3(8, 256), 256, SMB>>>((const __half*)p_xh, (const __half*)p_wq, bq,
                                         (const float*)p_kv, (const float*)p_ks,
                                         (__half*)p_att);
    // 3) output projection + gelu
    k_out<<<dim3(8, 256), 256, SMB>>>((const __half*)p_att, (const __half*)p_wo, bo, out);
}

// round 13
// speedup vs baseline: 1.5217x; 1.5217x over previous
#include <cuda_runtime.h>
#include <cuda_fp16.h>
#include <cstdint>

#define EPS 1e-6f
// B=8, S=4096, IN=1024, HD=1024, OUT=1024, M=32768

// ---------------- scratch (allocation-free device globals) ----------------
__device__ __half g_xh [33554432];  // fp16 x            [32768,1024] (64MB)
__device__ __half g_wqT[1048576];   // [N,K] transposed fp16
__device__ __half g_wkT[1048576];
__device__ __half g_wvT[1048576];
__device__ __half g_woT[1048576];
__device__ __half g_att[33554432];  // attn scratch fp16 (64MB)
__device__ float  g_KV[8192];       // [B, H*D]
__device__ float  g_KS[8192];

// ---------------- helpers ----------------
__device__ __forceinline__ uint32_t sptr(const void* p) {
    return (uint32_t)__cvta_generic_to_shared(p);
}
__device__ __forceinline__ void cpa16(uint32_t d, const void* s) {
    asm volatile("cp.async.cg.shared.global [%0], [%1], 16;\n" :: "r"(d), "l"(s));
}
__device__ __forceinline__ void cp_commit() { asm volatile("cp.async.commit_group;\n"); }
template<int N> __device__ __forceinline__ void cp_wait() {
    asm volatile("cp.async.wait_group %0;\n" :: "n"(N));
}
__device__ __forceinline__ void ldsm4(uint32_t& r0, uint32_t& r1, uint32_t& r2, uint32_t& r3,
                                      uint32_t a) {
    asm volatile("ldmatrix.sync.aligned.m8n8.x4.shared.b16 {%0,%1,%2,%3}, [%4];"
                 : "=r"(r0), "=r"(r1), "=r"(r2), "=r"(r3) : "r"(a));
}
__device__ __forceinline__ void mma16(float* c, const uint32_t* a, const uint32_t* b) {
    asm volatile(
        "mma.sync.aligned.m16n8k16.row.col.f32.f16.f16.f32 "
        "{%0,%1,%2,%3}, {%4,%5,%6,%7}, {%8,%9}, {%0,%1,%2,%3};"
        : "+f"(c[0]), "+f"(c[1]), "+f"(c[2]), "+f"(c[3])
        : "r"(a[0]), "r"(a[1]), "r"(a[2]), "r"(a[3]), "r"(b[0]), "r"(b[1]));
}
__device__ __forceinline__ float fmap(float x) {   // elu(x)+1
    return x > 0.f ? x + 1.f : __expf(x);
}
// tanh-approx gelu via sigmoid identity: gelu(x) = x - x/(exp(2z)+1),
// z = 0.7978845608*(x + 0.044715 x^3). Same math as tanhf version, ~1e-6 acc,
// ~8 instrs (2 MUFU) vs tanhf's branchy ~25.
__device__ __forceinline__ float gelu_t(float x) {
    float z2 = 1.5957691216057308f * (x + 0.044715f * x * x * x);
    float e  = __expf(z2);
    return x - x * __fdividef(1.f, e + 1.f);
}

// ---------------- prep kernels ----------------
__global__ void k_tohalf(const float4* __restrict__ src, __half2* __restrict__ dst, int n4) {
    int i = blockIdx.x * blockDim.x + threadIdx.x;
    if (i < n4) {
        float4 v = src[i];
        dst[2 * i]     = __floats2half2_rn(v.x, v.y);
        dst[2 * i + 1] = __floats2half2_rn(v.z, v.w);
    }
}
// transpose 1024x1024 [K][N] -> [N][K], convert to fp16; blockIdx.z picks matrix
__global__ void k_wt(const float* __restrict__ s0, __half* __restrict__ d0,
                     const float* __restrict__ s1, __half* __restrict__ d1,
                     const float* __restrict__ s2, __half* __restrict__ d2,
                     const float* __restrict__ s3, __half* __restrict__ d3)
{
    __shared__ float t[32][33];
    const float* src; __half* dst;
    switch (blockIdx.z) {
        case 0:  src = s0; dst = d0; break;
        case 1:  src = s1; dst = d1; break;
        case 2:  src = s2; dst = d2; break;
        default: src = s3; dst = d3; break;
    }
    int bx = blockIdx.x << 5, by = blockIdx.y << 5;
    int tx = threadIdx.x, ty = threadIdx.y;   // 32 x 8
#pragma unroll
    for (int i = 0; i < 4; i++)
        t[ty + i * 8][tx] = src[(size_t)(by + ty + i * 8) * 1024 + bx + tx];
    __syncthreads();
#pragma unroll
    for (int i = 0; i < 4; i++)
        dst[(size_t)(bx + ty + i * 8) * 1024 + by + tx] = __float2half_rn(t[tx][ty + i * 8]);
}
__global__ void k_zero(float* a, float* b, int n) {
    int i = blockIdx.x * blockDim.x + threadIdx.x;
    if (i < n) { a[i] = 0.f; b[i] = 0.f; }
}

// swizzled smem byte address of 16B chunk (r row of 128B, c chunk 0..7)
#define SWC(base, r, c) ((base) + (r) * 128 + (((c) ^ ((r) & 7)) << 4))

// ---------------- Kernel 1: K/V dual-GEMM + KV/Ksum reduction ----------------
// BM=128, BN=64, BK=64, 256 thr, warps 4(m)x2(n), warp tile 32x32
// smem/stage: A 16K + Bk 8K + Bv 8K = 32K; 3 stages = 96K; 2 CTA/SM
__global__ void __launch_bounds__(256) k_kv(
    const __half* __restrict__ X, const __half* __restrict__ WkT, const __half* __restrict__ WvT,
    const float* __restrict__ BK, const float* __restrict__ BV,
    float* __restrict__ KV, float* __restrict__ KS)
{
    extern __shared__ char sm[];
    const uint32_t smb = sptr(sm);
    const int tid = threadIdx.x, lane = tid & 31, wid = tid >> 5;
    const int wm = wid >> 1, wn = wid & 1;
    const int rowBase = blockIdx.y << 7;
    const int colBase = blockIdx.x << 6;

    float accK[2][4][4], accV[2][4][4];
#pragma unroll
    for (int i = 0; i < 2; i++)
#pragma unroll
        for (int j = 0; j < 4; j++)
#pragma unroll
            for (int c = 0; c < 4; c++) { accK[i][j][c] = 0.f; accV[i][j][c] = 0.f; }

    auto load_chunk = [&](int kt, int s) {
        const uint32_t sa  = smb + s * 32768;
        const uint32_t sbk = sa + 16384;
        const uint32_t sbv = sbk + 8192;
        const __half* gA = X   + (size_t)rowBase * 1024 + kt * 64;
        const __half* gK = WkT + (size_t)colBase * 1024 + kt * 64;
        const __half* gV = WvT + (size_t)colBase * 1024 + kt * 64;
#pragma unroll
        for (int l = 0; l < 4; l++) {
            int e = l * 256 + tid, r = e >> 3, c = e & 7;
            cpa16(SWC(sa, r, c), gA + (size_t)r * 1024 + c * 8);
        }
#pragma unroll
        for (int l = 0; l < 2; l++) {
            int e = l * 256 + tid, r = e >> 3, c = e & 7;
            cpa16(SWC(sbk, r, c), gK + (size_t)r * 1024 + c * 8);
            cpa16(SWC(sbv, r, c), gV + (size_t)r * 1024 + c * 8);
        }
        cp_commit();
    };

    load_chunk(0, 0);
    load_chunk(1, 1);

    // ldmatrix lane roles
    const int rA0 = wm * 32 + (lane & 15);        // + mi*16
    const int selA = lane >> 4;                   // chunk +0/+1
    const int cB0 = wn * 32 + (lane & 7) + ((lane >> 4) << 3);  // + pair*16
    const int selB = (lane >> 3) & 1;

    for (int kt = 0; kt < 16; kt++) {
        if (kt < 15) cp_wait<1>(); else cp_wait<0>();
        __syncthreads();
        const int s = kt % 3;
        const uint32_t sa  = smb + s * 32768;
        const uint32_t sbk = sa + 16384;
        const uint32_t sbv = sbk + 8192;
#pragma unroll
        for (int ks = 0; ks < 4; ks++) {
            uint32_t af[2][4], bk2[4][2], bv2[4][2];
#pragma unroll
            for (int mi = 0; mi < 2; mi++) {
                const int r = rA0 + mi * 16;
                ldsm4(af[mi][0], af[mi][1], af[mi][2], af[mi][3],
                      sa + r * 128 + (((2 * ks + selA) ^ (r & 7)) << 4));
            }
#pragma unroll
            for (int p = 0; p < 2; p++) {
                const int c = cB0 + p * 16;
                const uint32_t off = c * 128 + (((2 * ks + selB) ^ (c & 7)) << 4);
                ldsm4(bk2[2 * p][0], bk2[2 * p][1], bk2[2 * p + 1][0], bk2[2 * p + 1][1],
                      sbk + off);
                ldsm4(bv2[2 * p][0], bv2[2 * p][1], bv2[2 * p + 1][0], bv2[2 * p + 1][1],
                      sbv + off);
            }
            // overlap next-chunk cp.async issue with ks=0 LDSM latency
            if (ks == 0 && kt < 14) load_chunk(kt + 2, (kt + 2) % 3);
#pragma unroll
            for (int mi = 0; mi < 2; mi++)
#pragma unroll
                for (int ni = 0; ni < 4; ni++) {
                    mma16(accK[mi][ni], af[mi], bk2[ni]);
                    mma16(accV[mi][ni], af[mi], bv2[ni]);
                }
        }
    }

    // epilogue: K = elu+1, reduce K*v and K over the 128 s-rows of this block
    const int b = rowBase >> 12;
#pragma unroll
    for (int ni = 0; ni < 4; ni++) {
#pragma unroll
        for (int c = 0; c < 2; c++) {
            const int colg = colBase + wn * 32 + ni * 8 + 2 * (lane & 3) + c;
            const float bkc = BK[colg], bvc = BV[colg];
            float skv = 0.f, sk = 0.f;
#pragma unroll
            for (int mi = 0; mi < 2; mi++) {
                float kA = accK[mi][ni][c]     + bkc;
                float kB = accK[mi][ni][c + 2] + bkc;
                float vA = accV[mi][ni][c]     + bvc;
                float vB = accV[mi][ni][c + 2] + bvc;
                float KA = fmap(kA), KB = fmap(kB);
                skv += KA * vA + KB * vB;
                sk  += KA + KB;
            }
#pragma unroll
            for (int off = 16; off >= 4; off >>= 1) {
                skv += __shfl_xor_sync(0xffffffffu, skv, off);
                sk  += __shfl_xor_sync(0xffffffffu, sk,  off);
            }
            if (lane < 4) {
                atomicAdd(&KV[b * 1024 + colg], skv);
                atomicAdd(&KS[b * 1024 + colg], sk);
            }
        }
    }
}

// ---------------- Kernels 2/3 common mainloop ----------------
// BM=128, BN=128, BK=64, 256 thr, warps 2(m)x4(n), warp tile 64x32
// smem/stage: A 16K + B 16K = 32K; 3 stages = 96K; 2 CTA/SM
#define GEMM_MAIN(WT)                                                                   \
    extern __shared__ char sm[];                                                        \
    const uint32_t smb = sptr(sm);                                                      \
    const int tid = threadIdx.x, lane = tid & 31, wid = tid >> 5;                       \
    const int wm = wid >> 2, wn = wid & 3;                                              \
    const int rowBase = blockIdx.y << 7;                                                \
    const int colBase = blockIdx.x << 7;                                                \
    float acc[4][4][4];                                                                 \
    _Pragma("unroll") for (int i = 0; i < 4; i++)                                       \
    _Pragma("unroll") for (int j = 0; j < 4; j++)                                       \
    _Pragma("unroll") for (int c = 0; c < 4; c++) acc[i][j][c] = 0.f;                   \
    auto load_chunk = [&](int kt, int s) {                                              \
        const uint32_t sa = smb + s * 32768;                                            \
        const uint32_t sb = sa + 16384;                                                 \
        const __half* gA = A  + (size_t)rowBase * 1024 + kt * 64;                       \
        const __half* gB = WT + (size_t)colBase * 1024 + kt * 64;                       \
        _Pragma("unroll") for (int l = 0; l < 4; l++) {                                 \
            int e = l * 256 + tid, r = e >> 3, c = e & 7;                               \
            cpa16(SWC(sa, r, c), gA + (size_t)r * 1024 + c * 8);                        \
            cpa16(SWC(sb, r, c), gB + (size_t)r * 1024 + c * 8);                        \
        }                                                                               \
        cp_commit();                                                                    \
    };                                                                                  \
    load_chunk(0, 0);                                                                   \
    load_chunk(1, 1);                                                                   \
    const int rA0 = wm * 64 + (lane & 15);                                              \
    const int selA = lane >> 4;                                                         \
    const int cB0 = wn * 32 + (lane & 7) + ((lane >> 4) << 3);                          \
    const int selB = (lane >> 3) & 1;                                                   \
    for (int kt = 0; kt < 16; kt++) {                                                   \
        if (kt < 15) cp_wait<1>(); else cp_wait<0>();                                   \
        __syncthreads();                                                                \
        const int s = kt % 3;                                                           \
        const uint32_t sa = smb + s * 32768;                                            \
        const uint32_t sb = sa + 16384;                                                 \
        _Pragma("unroll") for (int ks = 0; ks < 4; ks++) {                              \
            uint32_t af[4][4], bf[4][2];                                                \
            _Pragma("unroll") for (int mi = 0; mi < 4; mi++) {                          \
                const int r = rA0 + mi * 16;                                            \
                ldsm4(af[mi][0], af[mi][1], af[mi][2], af[mi][3],                       \
                      sa + r * 128 + (((2 * ks + selA) ^ (r & 7)) << 4));               \
            }                                                                           \
            _Pragma("unroll") for (int p = 0; p < 2; p++) {                             \
                const int c = cB0 + p * 16;                                             \
                ldsm4(bf[2 * p][0], bf[2 * p][1], bf[2 * p + 1][0], bf[2 * p + 1][1],   \
                      sb + c * 128 + (((2 * ks + selB) ^ (c & 7)) << 4));               \
            }                                                                           \
            if (ks == 0 && kt < 14) load_chunk(kt + 2, (kt + 2) % 3);                   \
            _Pragma("unroll") for (int mi = 0; mi < 4; mi++)                            \
            _Pragma("unroll") for (int ni = 0; ni < 4; ni++)                            \
                mma16(acc[mi][ni], af[mi], bf[ni]);                                     \
        }                                                                               \
    }

// ---------------- Kernel 2: Q projection + attn epilogue (fp16 out) ----------------
__global__ void __launch_bounds__(256) k_q_attn(
    const __half* __restrict__ A, const __half* __restrict__ WT,
    const float* __restrict__ BQ, const float* __restrict__ KV,
    const float* __restrict__ KS, __half* __restrict__ ATT)
{
    GEMM_MAIN(WT)
    const int b = rowBase >> 12;
    const int g = lane >> 2;
#pragma unroll
    for (int mi = 0; mi < 4; mi++) {
        const int r0 = rowBase + wm * 64 + mi * 16 + g;
#pragma unroll
        for (int ni = 0; ni < 4; ni++) {
            const int c0 = colBase + wn * 32 + ni * 8 + 2 * (lane & 3);
            const float kv0 = KV[b * 1024 + c0], kv1 = KV[b * 1024 + c0 + 1];
            const float ks0 = KS[b * 1024 + c0], ks1 = KS[b * 1024 + c0 + 1];
            const float bq0 = BQ[c0], bq1 = BQ[c0 + 1];
#pragma unroll
            for (int h = 0; h < 2; h++) {
                const int r = r0 + 8 * h;
                float Q0 = fmap(acc[mi][ni][2 * h + 0] + bq0);
                float Q1 = fmap(acc[mi][ni][2 * h + 1] + bq1);
                float a0 = __fdividef(Q0 * kv0, Q0 * ks0 + EPS);
                float a1 = __fdividef(Q1 * kv1, Q1 * ks1 + EPS);
                *(__half2*)(&ATT[(size_t)r * 1024 + c0]) = __floats2half2_rn(a0, a1);
            }
        }
    }
}

// ---------------- Kernel 3: output projection + gelu (fp32 out) ----------------
__global__ void __launch_bounds__(256) k_out(
    const __half* __restrict__ A, const __half* __restrict__ WT,
    const float* __restrict__ BO, float* __restrict__ OUT)
{
    GEMM_MAIN(WT)
    const int g = lane >> 2;
#pragma unroll
    for (int mi = 0; mi < 4; mi++) {
        const int r0 = rowBase + wm * 64 + mi * 16 + g;
#pragma unroll
        for (int ni = 0; ni < 4; ni++) {
            const int c0 = colBase + wn * 32 + ni * 8 + 2 * (lane & 3);
            const float bo0 = BO[c0], bo1 = BO[c0 + 1];
#pragma unroll
            for (int h = 0; h < 2; h++) {
                const int r = r0 + 8 * h;
                float o0 = gelu_t(acc[mi][ni][2 * h + 0] + bo0);
                float o1 = gelu_t(acc[mi][ni][2 * h + 1] + bo1);
                *(float2*)(&OUT[(size_t)r * 1024 + c0]) = make_float2(o0, o1);
            }
        }
    }
}

// ---------------- host launcher ----------------
extern "C" void kernel_launch(void* const* d_in, const int* in_sizes, int n_in,
                              void* d_out, int out_size)
{
    const float* x  = (const float*)d_in[0];
    const float* wq = (const float*)d_in[1];
    const float* bq = (const float*)d_in[2];
    const float* wk = (const float*)d_in[3];
    const float* bk = (const float*)d_in[4];
    const float* wv = (const float*)d_in[5];
    const float* bv = (const float*)d_in[6];
    const float* wo = (const float*)d_in[7];
    const float* bo = (const float*)d_in[8];
    float* out = (float*)d_out;

    void *p_xh, *p_wq, *p_wk, *p_wv, *p_wo, *p_att, *p_kv, *p_ks;
    cudaGetSymbolAddress(&p_xh,  g_xh);
    cudaGetSymbolAddress(&p_wq,  g_wqT);
    cudaGetSymbolAddress(&p_wk,  g_wkT);
    cudaGetSymbolAddress(&p_wv,  g_wvT);
    cudaGetSymbolAddress(&p_wo,  g_woT);
    cudaGetSymbolAddress(&p_att, g_att);
    cudaGetSymbolAddress(&p_kv,  g_KV);
    cudaGetSymbolAddress(&p_ks,  g_KS);

    const int SMB = 98304;   // 3 stages x 32K
    cudaFuncSetAttribute(k_kv,     cudaFuncAttributeMaxDynamicSharedMemorySize, SMB);
    cudaFuncSetAttribute(k_q_attn, cudaFuncAttributeMaxDynamicSharedMemorySize, SMB);
    cudaFuncSetAttribute(k_out,    cudaFuncAttributeMaxDynamicSharedMemorySize, SMB);

    // prep: x -> fp16; transpose+convert weights to [N,K] fp16; zero accumulators
    k_tohalf<<<32768, 256>>>((const float4*)x, (__half2*)p_xh, 8388608);
    k_wt<<<dim3(32, 32, 4), dim3(32, 8)>>>(wq, (__half*)p_wq, wk, (__half*)p_wk,
                                           wv, (__half*)p_wv, wo, (__half*)p_wo);
    k_zero<<<8, 1024>>>((float*)p_kv, (float*)p_ks, 8192);

    // 1) K,V projections + KV/Ksum reduction (K,V never materialized)
    k_kv<<<dim3(16, 256), 256, SMB>>>((const __half*)p_xh,
                                      (const __half*)p_wk, (const __half*)p_wv,
                                      bk, bv, (float*)p_kv, (float*)p_ks);
    // 2) Q projection + linear-attention epilogue -> attn scratch (fp16)
    k_q_attn<<<dim3(8, 256), 256, SMB>>>((const __half*)p_xh, (const __half*)p_wq, bq,
                                         (const float*)p_kv, (const float*)p_ks,
                                         (__half*)p_att);
    // 3) output projection + gelu
    k_out<<<dim3(8, 256), 256, SMB>>>((const __half*)p_att, (const __half*)p_wo, bo, out);
}

// round 14
// speedup vs baseline: 1.5256x; 1.0025x over previous
#include <cuda_runtime.h>
#include <cuda_fp16.h>
#include <cstdint>

#define EPS 1e-6f
// B=8, S=4096, IN=1024, HD=1024, OUT=1024, M=32768

// ---------------- scratch (allocation-free device globals) ----------------
__device__ __half g_xh [33554432];  // fp16 x            [32768,1024] (64MB)
__device__ __half g_wqT[1048576];   // [N,K] transposed fp16
__device__ __half g_wkT[1048576];
__device__ __half g_wvT[1048576];
__device__ __half g_woT[1048576];
__device__ __half g_att[33554432];  // attn scratch fp16 (64MB)
__device__ float  g_KV[8192];       // [B, H*D]
__device__ float  g_KS[8192];

// ---------------- helpers ----------------
__device__ __forceinline__ uint32_t sptr(const void* p) {
    return (uint32_t)__cvta_generic_to_shared(p);
}
__device__ __forceinline__ void cpa16(uint32_t d, const void* s) {
    asm volatile("cp.async.cg.shared.global [%0], [%1], 16;\n" :: "r"(d), "l"(s));
}
__device__ __forceinline__ void cp_commit() { asm volatile("cp.async.commit_group;\n"); }
template<int N> __device__ __forceinline__ void cp_wait() {
    asm volatile("cp.async.wait_group %0;\n" :: "n"(N));
}
__device__ __forceinline__ void ldsm4(uint32_t& r0, uint32_t& r1, uint32_t& r2, uint32_t& r3,
                                      uint32_t a) {
    asm volatile("ldmatrix.sync.aligned.m8n8.x4.shared.b16 {%0,%1,%2,%3}, [%4];"
                 : "=r"(r0), "=r"(r1), "=r"(r2), "=r"(r3) : "r"(a));
}
__device__ __forceinline__ void mma16(float* c, const uint32_t* a, const uint32_t* b) {
    asm volatile(
        "mma.sync.aligned.m16n8k16.row.col.f32.f16.f16.f32 "
        "{%0,%1,%2,%3}, {%4,%5,%6,%7}, {%8,%9}, {%0,%1,%2,%3};"
        : "+f"(c[0]), "+f"(c[1]), "+f"(c[2]), "+f"(c[3])
        : "r"(a[0]), "r"(a[1]), "r"(a[2]), "r"(a[3]), "r"(b[0]), "r"(b[1]));
}
__device__ __forceinline__ float fmap(float x) {   // elu(x)+1
    return x > 0.f ? x + 1.f : __expf(x);
}
// tanh-approx gelu via sigmoid identity: gelu(x) = x - x/(exp(2z)+1),
// z = 0.7978845608*(x + 0.044715 x^3). Same math as tanhf version, ~1e-6 acc.
__device__ __forceinline__ float gelu_t(float x) {
    float z2 = 1.5957691216057308f * (x + 0.044715f * x * x * x);
    float e  = __expf(z2);
    return x - x * __fdividef(1.f, e + 1.f);
}

// ---------------- prep kernels ----------------
// x -> fp16 copy; first 32 blocks also zero the KV/KS accumulators
__global__ void k_tohalf(const float4* __restrict__ src, __half2* __restrict__ dst, int n4,
                         float* __restrict__ KV, float* __restrict__ KS) {
    int i = blockIdx.x * blockDim.x + threadIdx.x;
    if (blockIdx.x < 32) {
        int j = blockIdx.x * 256 + threadIdx.x;   // 8192 entries
        KV[j] = 0.f;
        KS[j] = 0.f;
    }
    if (i < n4) {
        float4 v = src[i];
        dst[2 * i]     = __floats2half2_rn(v.x, v.y);
        dst[2 * i + 1] = __floats2half2_rn(v.z, v.w);
    }
}
// transpose 1024x1024 [K][N] -> [N][K], convert to fp16; blockIdx.z picks matrix
__global__ void k_wt(const float* __restrict__ s0, __half* __restrict__ d0,
                     const float* __restrict__ s1, __half* __restrict__ d1,
                     const float* __restrict__ s2, __half* __restrict__ d2,
                     const float* __restrict__ s3, __half* __restrict__ d3)
{
    __shared__ float t[32][33];
    const float* src; __half* dst;
    switch (blockIdx.z) {
        case 0:  src = s0; dst = d0; break;
        case 1:  src = s1; dst = d1; break;
        case 2:  src = s2; dst = d2; break;
        default: src = s3; dst = d3; break;
    }
    int bx = blockIdx.x << 5, by = blockIdx.y << 5;
    int tx = threadIdx.x, ty = threadIdx.y;   // 32 x 8
#pragma unroll
    for (int i = 0; i < 4; i++)
        t[ty + i * 8][tx] = src[(size_t)(by + ty + i * 8) * 1024 + bx + tx];
    __syncthreads();
#pragma unroll
    for (int i = 0; i < 4; i++)
        dst[(size_t)(bx + ty + i * 8) * 1024 + by + tx] = __float2half_rn(t[tx][ty + i * 8]);
}

// swizzled smem byte address of 16B chunk (r row of 128B, c chunk 0..7)
#define SWC(base, r, c) ((base) + (r) * 128 + (((c) ^ ((r) & 7)) << 4))

// ---------------- Kernel 1: K/V dual-GEMM + KV/Ksum reduction ----------------
// BM=128, BN=64, BK=64, 256 thr, warps 4(m)x2(n), warp tile 32x32
// smem/stage: A 16K + Bk 8K + Bv 8K = 32K; 3 stages = 96K; 2 CTA/SM
__global__ void __launch_bounds__(256) k_kv(
    const __half* __restrict__ X, const __half* __restrict__ WkT, const __half* __restrict__ WvT,
    const float* __restrict__ BK, const float* __restrict__ BV,
    float* __restrict__ KV, float* __restrict__ KS)
{
    extern __shared__ char sm[];
    const uint32_t smb = sptr(sm);
    const int tid = threadIdx.x, lane = tid & 31, wid = tid >> 5;
    const int wm = wid >> 1, wn = wid & 1;
    const int rowBase = blockIdx.y << 7;
    const int colBase = blockIdx.x << 6;

    float accK[2][4][4], accV[2][4][4];
#pragma unroll
    for (int i = 0; i < 2; i++)
#pragma unroll
        for (int j = 0; j < 4; j++)
#pragma unroll
            for (int c = 0; c < 4; c++) { accK[i][j][c] = 0.f; accV[i][j][c] = 0.f; }

    auto load_chunk = [&](int kt, int s) {
        const uint32_t sa  = smb + s * 32768;
        const uint32_t sbk = sa + 16384;
        const uint32_t sbv = sbk + 8192;
        const __half* gA = X   + (size_t)rowBase * 1024 + kt * 64;
        const __half* gK = WkT + (size_t)colBase * 1024 + kt * 64;
        const __half* gV = WvT + (size_t)colBase * 1024 + kt * 64;
#pragma unroll
        for (int l = 0; l < 4; l++) {
            int e = l * 256 + tid, r = e >> 3, c = e & 7;
            cpa16(SWC(sa, r, c), gA + (size_t)r * 1024 + c * 8);
        }
#pragma unroll
        for (int l = 0; l < 2; l++) {
            int e = l * 256 + tid, r = e >> 3, c = e & 7;
            cpa16(SWC(sbk, r, c), gK + (size_t)r * 1024 + c * 8);
            cpa16(SWC(sbv, r, c), gV + (size_t)r * 1024 + c * 8);
        }
        cp_commit();
    };

    load_chunk(0, 0);
    load_chunk(1, 1);

    // ldmatrix lane roles
    const int rA0 = wm * 32 + (lane & 15);        // + mi*16
    const int selA = lane >> 4;                   // chunk +0/+1
    const int cB0 = wn * 32 + (lane & 7) + ((lane >> 4) << 3);  // + pair*16
    const int selB = (lane >> 3) & 1;

    for (int kt = 0; kt < 16; kt++) {
        if (kt < 15) cp_wait<1>(); else cp_wait<0>();
        __syncthreads();
        const int s = kt % 3;
        const uint32_t sa  = smb + s * 32768;
        const uint32_t sbk = sa + 16384;
        const uint32_t sbv = sbk + 8192;
#pragma unroll
        for (int ks = 0; ks < 4; ks++) {
            uint32_t af[2][4], bk2[4][2], bv2[4][2];
#pragma unroll
            for (int mi = 0; mi < 2; mi++) {
                const int r = rA0 + mi * 16;
                ldsm4(af[mi][0], af[mi][1], af[mi][2], af[mi][3],
                      sa + r * 128 + (((2 * ks + selA) ^ (r & 7)) << 4));
            }
#pragma unroll
            for (int p = 0; p < 2; p++) {
                const int c = cB0 + p * 16;
                const uint32_t off = c * 128 + (((2 * ks + selB) ^ (c & 7)) << 4);
                ldsm4(bk2[2 * p][0], bk2[2 * p][1], bk2[2 * p + 1][0], bk2[2 * p + 1][1],
                      sbk + off);
                ldsm4(bv2[2 * p][0], bv2[2 * p][1], bv2[2 * p + 1][0], bv2[2 * p + 1][1],
                      sbv + off);
            }
            // overlap next-chunk cp.async issue with ks=0 LDSM latency
            if (ks == 0 && kt < 14) load_chunk(kt + 2, (kt + 2) % 3);
#pragma unroll
            for (int mi = 0; mi < 2; mi++)
#pragma unroll
                for (int ni = 0; ni < 4; ni++) {
                    mma16(accK[mi][ni], af[mi], bk2[ni]);
                    mma16(accV[mi][ni], af[mi], bv2[ni]);
                }
        }
    }

    // epilogue: K = elu+1, reduce K*v and K over the 128 s-rows of this block
    const int b = rowBase >> 12;
#pragma unroll
    for (int ni = 0; ni < 4; ni++) {
#pragma unroll
        for (int c = 0; c < 2; c++) {
            const int colg = colBase + wn * 32 + ni * 8 + 2 * (lane & 3) + c;
            const float bkc = BK[colg], bvc = BV[colg];
            float skv = 0.f, sk = 0.f;
#pragma unroll
            for (int mi = 0; mi < 2; mi++) {
                float kA = accK[mi][ni][c]     + bkc;
                float kB = accK[mi][ni][c + 2] + bkc;
                float vA = accV[mi][ni][c]     + bvc;
                float vB = accV[mi][ni][c + 2] + bvc;
                float KA = fmap(kA), KB = fmap(kB);
                skv += KA * vA + KB * vB;
                sk  += KA + KB;
            }
#pragma unroll
            for (int off = 16; off >= 4; off >>= 1) {
                skv += __shfl_xor_sync(0xffffffffu, skv, off);
                sk  += __shfl_xor_sync(0xffffffffu, sk,  off);
            }
            if (lane < 4) {
                atomicAdd(&KV[b * 1024 + colg], skv);
                atomicAdd(&KS[b * 1024 + colg], sk);
            }
        }
    }
}

// ---------------- Kernels 2/3 common mainloop ----------------
// BM=128, BN=128, BK=64, 256 thr, warps 2(m)x4(n), warp tile 64x32
// smem/stage: A 16K + B 16K = 32K; 3 stages = 96K; 2 CTA/SM
#define GEMM_MAIN(WT)                                                                   \
    extern __shared__ char sm[];                                                        \
    const uint32_t smb = sptr(sm);                                                      \
    const int tid = threadIdx.x, lane = tid & 31, wid = tid >> 5;                       \
    const int wm = wid >> 2, wn = wid & 3;                                              \
    const int rowBase = blockIdx.y << 7;                                                \
    const int colBase = blockIdx.x << 7;                                                \
    float acc[4][4][4];                                                                 \
    _Pragma("unroll") for (int i = 0; i < 4; i++)                                       \
    _Pragma("unroll") for (int j = 0; j < 4; j++)                                       \
    _Pragma("unroll") for (int c = 0; c < 4; c++) acc[i][j][c] = 0.f;                   \
    auto load_chunk = [&](int kt, int s) {                                              \
        const uint32_t sa = smb + s * 32768;                                            \
        const uint32_t sb = sa + 16384;                                                 \
        const __half* gA = A  + (size_t)rowBase * 1024 + kt * 64;                       \
        const __half* gB = WT + (size_t)colBase * 1024 + kt * 64;                       \
        _Pragma("unroll") for (int l = 0; l < 4; l++) {                                 \
            int e = l * 256 + tid, r = e >> 3, c = e & 7;                               \
            cpa16(SWC(sa, r, c), gA + (size_t)r * 1024 + c * 8);                        \
            cpa16(SWC(sb, r, c), gB + (size_t)r * 1024 + c * 8);                        \
        }                                                                               \
        cp_commit();                                                                    \
    };                                                                                  \
    load_chunk(0, 0);                                                                   \
    load_chunk(1, 1);                                                                   \
    const int rA0 = wm * 64 + (lane & 15);                                              \
    const int selA = lane >> 4;                                                         \
    const int cB0 = wn * 32 + (lane & 7) + ((lane >> 4) << 3);                          \
    const int selB = (lane >> 3) & 1;                                                   \
    for (int kt = 0; kt < 16; kt++) {                                                   \
        if (kt < 15) cp_wait<1>(); else cp_wait<0>();                                   \
        __syncthreads();                                                                \
        const int s = kt % 3;                                                           \
        const uint32_t sa = smb + s * 32768;                                            \
        const uint32_t sb = sa + 16384;                                                 \
        _Pragma("unroll") for (int ks = 0; ks < 4; ks++) {                              \
            uint32_t af[4][4], bf[4][2];                                                \
            _Pragma("unroll") for (int mi = 0; mi < 4; mi++) {                          \
                const int r = rA0 + mi * 16;                                            \
                ldsm4(af[mi][0], af[mi][1], af[mi][2], af[mi][3],                       \
                      sa + r * 128 + (((2 * ks + selA) ^ (r & 7)) << 4));               \
            }                                                                           \
            _Pragma("unroll") for (int p = 0; p < 2; p++) {                             \
                const int c = cB0 + p * 16;                                             \
                ldsm4(bf[2 * p][0], bf[2 * p][1], bf[2 * p + 1][0], bf[2 * p + 1][1],   \
                      sb + c * 128 + (((2 * ks + selB) ^ (c & 7)) << 4));               \
            }                                                                           \
            if (ks == 0 && kt < 14) load_chunk(kt + 2, (kt + 2) % 3);                   \
            _Pragma("unroll") for (int mi = 0; mi < 4; mi++)                            \
            _Pragma("unroll") for (int ni = 0; ni < 4; ni++)                            \
                mma16(acc[mi][ni], af[mi], bf[ni]);                                     \
        }                                                                               \
    }

// ---------------- Kernel 2: Q projection + attn epilogue (fp16 out) ----------------
__global__ void __launch_bounds__(256) k_q_attn(
    const __half* __restrict__ A, const __half* __restrict__ WT,
    const float* __restrict__ BQ, const float* __restrict__ KV,
    const float* __restrict__ KS, __half* __restrict__ ATT)
{
    GEMM_MAIN(WT)
    const int b = rowBase >> 12;
    const int g = lane >> 2;
    // ni-outer: hoist KV/KS/BQ loads (were re-loaded per mi)
#pragma unroll
    for (int ni = 0; ni < 4; ni++) {
        const int c0 = colBase + wn * 32 + ni * 8 + 2 * (lane & 3);
        const float kv0 = KV[b * 1024 + c0], kv1 = KV[b * 1024 + c0 + 1];
        const float ks0 = KS[b * 1024 + c0], ks1 = KS[b * 1024 + c0 + 1];
        const float bq0 = BQ[c0], bq1 = BQ[c0 + 1];
#pragma unroll
        for (int mi = 0; mi < 4; mi++) {
            const int r0 = rowBase + wm * 64 + mi * 16 + g;
#pragma unroll
            for (int h = 0; h < 2; h++) {
                const int r = r0 + 8 * h;
                float Q0 = fmap(acc[mi][ni][2 * h + 0] + bq0);
                float Q1 = fmap(acc[mi][ni][2 * h + 1] + bq1);
                float a0 = __fdividef(Q0 * kv0, Q0 * ks0 + EPS);
                float a1 = __fdividef(Q1 * kv1, Q1 * ks1 + EPS);
                *(__half2*)(&ATT[(size_t)r * 1024 + c0]) = __floats2half2_rn(a0, a1);
            }
        }
    }
}

// ---------------- Kernel 3: output projection + gelu (fp32 out) ----------------
__global__ void __launch_bounds__(256) k_out(
    const __half* __restrict__ A, const __half* __restrict__ WT,
    const float* __restrict__ BO, float* __restrict__ OUT)
{
    GEMM_MAIN(WT)
    const int g = lane >> 2;
#pragma unroll
    for (int ni = 0; ni < 4; ni++) {
        const int c0 = colBase + wn * 32 + ni * 8 + 2 * (lane & 3);
        const float bo0 = BO[c0], bo1 = BO[c0 + 1];
#pragma unroll
        for (int mi = 0; mi < 4; mi++) {
            const int r0 = rowBase + wm * 64 + mi * 16 + g;
#pragma unroll
            for (int h = 0; h < 2; h++) {
                const int r = r0 + 8 * h;
                float o0 = gelu_t(acc[mi][ni][2 * h + 0] + bo0);
                float o1 = gelu_t(acc[mi][ni][2 * h + 1] + bo1);
                *(float2*)(&OUT[(size_t)r * 1024 + c0]) = make_float2(o0, o1);
            }
        }
    }
}

// ---------------- host launcher ----------------
extern "C" void kernel_launch(void* const* d_in, const int* in_sizes, int n_in,
                              void* d_out, int out_size)
{
    const float* x  = (const float*)d_in[0];
    const float* wq = (const float*)d_in[1];
    const float* bq = (const float*)d_in[2];
    const float* wk = (const float*)d_in[3];
    const float* bk = (const float*)d_in[4];
    const float* wv = (const float*)d_in[5];
    const float* bv = (const float*)d_in[6];
    const float* wo = (const float*)d_in[7];
    const float* bo = (const float*)d_in[8];
    float* out = (float*)d_out;

    void *p_xh, *p_wq, *p_wk, *p_wv, *p_wo, *p_att, *p_kv, *p_ks;
    cudaGetSymbolAddress(&p_xh,  g_xh);
    cudaGetSymbolAddress(&p_wq,  g_wqT);
    cudaGetSymbolAddress(&p_wk,  g_wkT);
    cudaGetSymbolAddress(&p_wv,  g_wvT);
    cudaGetSymbolAddress(&p_wo,  g_woT);
    cudaGetSymbolAddress(&p_att, g_att);
    cudaGetSymbolAddress(&p_kv,  g_KV);
    cudaGetSymbolAddress(&p_ks,  g_KS);

    const int SMB = 98304;   // 3 stages x 32K
    cudaFuncSetAttribute(k_kv,     cudaFuncAttributeMaxDynamicSharedMemorySize, SMB);
    cudaFuncSetAttribute(k_q_attn, cudaFuncAttributeMaxDynamicSharedMemorySize, SMB);
    cudaFuncSetAttribute(k_out,    cudaFuncAttributeMaxDynamicSharedMemorySize, SMB);

    // prep: x -> fp16 (+ zero accumulators); transpose+convert weights to [N,K] fp16
    k_tohalf<<<32768, 256>>>((const float4*)x, (__half2*)p_xh, 8388608,
                             (float*)p_kv, (float*)p_ks);
    k_wt<<<dim3(32, 32, 4), dim3(32, 8)>>>(wq, (__half*)p_wq, wk, (__half*)p_wk,
                                           wv, (__half*)p_wv, wo, (__half*)p_wo);

    // 1) K,V projections + KV/Ksum reduction (K,V never materialized)
    k_kv<<<dim3(16, 256), 256, SMB>>>((const __half*)p_xh,
                                      (const __half*)p_wk, (const __half*)p_wv,
                                      bk, bv, (float*)p_kv, (float*)p_ks);
    // 2) Q projection + linear-attention epilogue -> attn scratch (fp16)
    k_q_attn<<<dim3(8, 256), 256, SMB>>>((const __half*)p_xh, (const __half*)p_wq, bq,
                                         (const float*)p_kv, (const float*)p_ks,
                                         (__half*)p_att);
    // 3) output projection + gelu
    k_out<<<dim3(8, 256), 256, SMB>>>((const __half*)p_att, (const __half*)p_wo, bo, out);
}

// round 15
// speedup vs baseline: 1.5496x; 1.0158x over previous
#include <cuda_runtime.h>
#include <cuda_fp16.h>
#include <cstdint>

#define EPS 1e-6f
// B=8, S=4096, IN=1024, HD=1024, OUT=1024, M=32768

// ---------------- scratch (allocation-free device globals) ----------------
__device__ __half g_xh [33554432];  // fp16 x            [32768,1024] (64MB)
__device__ __half g_wqT[1048576];   // [N,K] transposed fp16
__device__ __half g_wkT[1048576];
__device__ __half g_wvT[1048576];
__device__ __half g_woT[1048576];
__device__ __half g_att[33554432];  // attn scratch fp16 (64MB)
__device__ float  g_KV[8192];       // [B, H*D]
__device__ float  g_KS[8192];

// ---------------- helpers ----------------
__device__ __forceinline__ uint32_t sptr(const void* p) {
    return (uint32_t)__cvta_generic_to_shared(p);
}
__device__ __forceinline__ void cpa16(uint32_t d, const void* s) {
    asm volatile("cp.async.cg.shared.global [%0], [%1], 16;\n" :: "r"(d), "l"(s));
}
__device__ __forceinline__ void cp_commit() { asm volatile("cp.async.commit_group;\n"); }
template<int N> __device__ __forceinline__ void cp_wait() {
    asm volatile("cp.async.wait_group %0;\n" :: "n"(N));
}
__device__ __forceinline__ void ldsm4(uint32_t& r0, uint32_t& r1, uint32_t& r2, uint32_t& r3,
                                      uint32_t a) {
    asm volatile("ldmatrix.sync.aligned.m8n8.x4.shared.b16 {%0,%1,%2,%3}, [%4];"
                 : "=r"(r0), "=r"(r1), "=r"(r2), "=r"(r3) : "r"(a));
}
__device__ __forceinline__ void mma16(float* c, const uint32_t* a, const uint32_t* b) {
    asm volatile(
        "mma.sync.aligned.m16n8k16.row.col.f32.f16.f16.f32 "
        "{%0,%1,%2,%3}, {%4,%5,%6,%7}, {%8,%9}, {%0,%1,%2,%3};"
        : "+f"(c[0]), "+f"(c[1]), "+f"(c[2]), "+f"(c[3])
        : "r"(a[0]), "r"(a[1]), "r"(a[2]), "r"(a[3]), "r"(b[0]), "r"(b[1]));
}
__device__ __forceinline__ float fmap(float x) {   // elu(x)+1
    return x > 0.f ? x + 1.f : __expf(x);
}
// tanh-approx gelu via sigmoid identity: gelu(x) = x - x/(exp(2z)+1)
__device__ __forceinline__ float gelu_t(float x) {
    float z2 = 1.5957691216057308f * (x + 0.044715f * x * x * x);
    float e  = __expf(z2);
    return x - x * __fdividef(1.f, e + 1.f);
}

// ---------------- prep kernels ----------------
// x -> fp16 copy; first 32 blocks also zero the KV/KS accumulators
__global__ void k_tohalf(const float4* __restrict__ src, __half2* __restrict__ dst, int n4,
                         float* __restrict__ KV, float* __restrict__ KS) {
    int i = blockIdx.x * blockDim.x + threadIdx.x;
    if (blockIdx.x < 32) {
        int j = blockIdx.x * 256 + threadIdx.x;   // 8192 entries
        KV[j] = 0.f;
        KS[j] = 0.f;
    }
    if (i < n4) {
        float4 v = src[i];
        dst[2 * i]     = __floats2half2_rn(v.x, v.y);
        dst[2 * i + 1] = __floats2half2_rn(v.z, v.w);
    }
}
// transpose 1024x1024 [K][N] -> [N][K], convert to fp16; blockIdx.z picks matrix
__global__ void k_wt(const float* __restrict__ s0, __half* __restrict__ d0,
                     const float* __restrict__ s1, __half* __restrict__ d1,
                     const float* __restrict__ s2, __half* __restrict__ d2,
                     const float* __restrict__ s3, __half* __restrict__ d3)
{
    __shared__ float t[32][33];
    const float* src; __half* dst;
    switch (blockIdx.z) {
        case 0:  src = s0; dst = d0; break;
        case 1:  src = s1; dst = d1; break;
        case 2:  src = s2; dst = d2; break;
        default: src = s3; dst = d3; break;
    }
    int bx = blockIdx.x << 5, by = blockIdx.y << 5;
    int tx = threadIdx.x, ty = threadIdx.y;   // 32 x 8
#pragma unroll
    for (int i = 0; i < 4; i++)
        t[ty + i * 8][tx] = src[(size_t)(by + ty + i * 8) * 1024 + bx + tx];
    __syncthreads();
#pragma unroll
    for (int i = 0; i < 4; i++)
        dst[(size_t)(bx + ty + i * 8) * 1024 + by + tx] = __float2half_rn(t[tx][ty + i * 8]);
}

// swizzled smem byte address of 16B chunk (r row of 128B, c chunk 0..7)
#define SWC(base, r, c) ((base) + (r) * 128 + (((c) ^ ((r) & 7)) << 4))

// ---------------- Kernel 1: K/V dual-GEMM + KV/Ksum reduction ----------------
// BM=128, BN=64, BK=64, 256 thr, warps 4(m)x2(n), warp tile 32x32
// smem/stage: A 16K + Bk 8K + Bv 8K = 32K; 3 stages = 96K; 2 CTA/SM
__global__ void __launch_bounds__(256, 2) k_kv(
    const __half* __restrict__ X, const __half* __restrict__ WkT, const __half* __restrict__ WvT,
    const float* __restrict__ BK, const float* __restrict__ BV,
    float* __restrict__ KV, float* __restrict__ KS)
{
    extern __shared__ char sm[];
    const uint32_t smb = (sptr(sm) + 127u) & ~127u;   // 128B-aligned: XOR addressing valid
    const int tid = threadIdx.x, lane = tid & 31, wid = tid >> 5;
    const int wm = wid >> 1, wn = wid & 1;
    const int rowBase = blockIdx.y << 7;
    const int colBase = blockIdx.x << 6;

    float accK[2][4][4], accV[2][4][4];
#pragma unroll
    for (int i = 0; i < 2; i++)
#pragma unroll
        for (int j = 0; j < 4; j++)
#pragma unroll
            for (int c = 0; c < 4; c++) { accK[i][j][c] = 0.f; accV[i][j][c] = 0.f; }

    auto load_chunk = [&](int kt, int s) {
        const uint32_t sa  = smb + s * 32768;
        const uint32_t sbk = sa + 16384;
        const uint32_t sbv = sbk + 8192;
        const __half* gA = X   + (size_t)rowBase * 1024 + kt * 64;
        const __half* gK = WkT + (size_t)colBase * 1024 + kt * 64;
        const __half* gV = WvT + (size_t)colBase * 1024 + kt * 64;
#pragma unroll
        for (int l = 0; l < 4; l++) {
            int e = l * 256 + tid, r = e >> 3, c = e & 7;
            cpa16(SWC(sa, r, c), gA + (size_t)r * 1024 + c * 8);
        }
#pragma unroll
        for (int l = 0; l < 2; l++) {
            int e = l * 256 + tid, r = e >> 3, c = e & 7;
            cpa16(SWC(sbk, r, c), gK + (size_t)r * 1024 + c * 8);
            cpa16(SWC(sbv, r, c), gV + (size_t)r * 1024 + c * 8);
        }
        cp_commit();
    };

    load_chunk(0, 0);
    load_chunk(1, 1);

    // ldmatrix lane roles + precomputed swizzle-folded relative addresses
    const int rA0 = wm * 32 + (lane & 15);
    const int selA = lane >> 4;
    const int cB0 = wn * 32 + (lane & 7) + ((lane >> 4) << 3);
    const int selB = (lane >> 3) & 1;
    uint32_t aRel[2], bRel[2];
#pragma unroll
    for (int mi = 0; mi < 2; mi++) {
        const int r = rA0 + mi * 16;
        aRel[mi] = r * 128 + ((selA ^ (r & 7)) << 4);
    }
#pragma unroll
    for (int p = 0; p < 2; p++) {
        const int c = cB0 + p * 16;
        bRel[p] = c * 128 + ((selB ^ (c & 7)) << 4);
    }

    for (int kt = 0; kt < 16; kt++) {
        if (kt < 15) cp_wait<1>(); else cp_wait<0>();
        __syncthreads();
        const int s = kt % 3;
        const uint32_t sa  = smb + s * 32768;
        const uint32_t sbk = sa + 16384;
        const uint32_t sbv = sbk + 8192;
#pragma unroll
        for (int ks = 0; ks < 4; ks++) {
            const uint32_t xk = ks << 5;     // (2ks)<<4: folds into chunk bits via XOR
            uint32_t af[2][4], bk2[4][2], bv2[4][2];
#pragma unroll
            for (int mi = 0; mi < 2; mi++)
                ldsm4(af[mi][0], af[mi][1], af[mi][2], af[mi][3],
                      (sa + aRel[mi]) ^ xk);
#pragma unroll
            for (int p = 0; p < 2; p++) {
                const uint32_t off = bRel[p] ^ xk;
                ldsm4(bk2[2 * p][0], bk2[2 * p][1], bk2[2 * p + 1][0], bk2[2 * p + 1][1],
                      sbk + off);
                ldsm4(bv2[2 * p][0], bv2[2 * p][1], bv2[2 * p + 1][0], bv2[2 * p + 1][1],
                      sbv + off);
            }
            // overlap next-chunk cp.async issue with ks=0 LDSM latency
            if (ks == 0 && kt < 14) load_chunk(kt + 2, (kt + 2) % 3);
#pragma unroll
            for (int mi = 0; mi < 2; mi++)
#pragma unroll
                for (int ni = 0; ni < 4; ni++) {
                    mma16(accK[mi][ni], af[mi], bk2[ni]);
                    mma16(accV[mi][ni], af[mi], bv2[ni]);
                }
        }
    }

    // epilogue: K = elu+1, reduce K*v and K over the 128 s-rows of this block
    const int b = rowBase >> 12;
#pragma unroll
    for (int ni = 0; ni < 4; ni++) {
#pragma unroll
        for (int c = 0; c < 2; c++) {
            const int colg = colBase + wn * 32 + ni * 8 + 2 * (lane & 3) + c;
            const float bkc = BK[colg], bvc = BV[colg];
            float skv = 0.f, sk = 0.f;
#pragma unroll
            for (int mi = 0; mi < 2; mi++) {
                float kA = accK[mi][ni][c]     + bkc;
                float kB = accK[mi][ni][c + 2] + bkc;
                float vA = accV[mi][ni][c]     + bvc;
                float vB = accV[mi][ni][c + 2] + bvc;
                float KA = fmap(kA), KB = fmap(kB);
                skv += KA * vA + KB * vB;
                sk  += KA + KB;
            }
#pragma unroll
            for (int off = 16; off >= 4; off >>= 1) {
                skv += __shfl_xor_sync(0xffffffffu, skv, off);
                sk  += __shfl_xor_sync(0xffffffffu, sk,  off);
            }
            if (lane < 4) {
                atomicAdd(&KV[b * 1024 + colg], skv);
                atomicAdd(&KS[b * 1024 + colg], sk);
            }
        }
    }
}

// ---------------- Kernels 2/3 common mainloop ----------------
// BM=128, BN=128, BK=64, 256 thr, warps 2(m)x4(n), warp tile 64x32
// smem/stage: A 16K + B 16K = 32K; 3 stages = 96K; 2 CTA/SM
#define GEMM_MAIN(WT)                                                                   \
    extern __shared__ char sm[];                                                        \
    const uint32_t smb = (sptr(sm) + 127u) & ~127u;                                     \
    const int tid = threadIdx.x, lane = tid & 31, wid = tid >> 5;                       \
    const int wm = wid >> 2, wn = wid & 3;                                              \
    const int rowBase = blockIdx.y << 7;                                                \
    const int colBase = blockIdx.x << 7;                                                \
    float acc[4][4][4];                                                                 \
    _Pragma("unroll") for (int i = 0; i < 4; i++)                                       \
    _Pragma("unroll") for (int j = 0; j < 4; j++)                                       \
    _Pragma("unroll") for (int c = 0; c < 4; c++) acc[i][j][c] = 0.f;                   \
    auto load_chunk = [&](int kt, int s) {                                              \
        const uint32_t sa = smb + s * 32768;                                            \
        const uint32_t sb = sa + 16384;                                                 \
        const __half* gA = A  + (size_t)rowBase * 1024 + kt * 64;                       \
        const __half* gB = WT + (size_t)colBase * 1024 + kt * 64;                       \
        _Pragma("unroll") for (int l = 0; l < 4; l++) {                                 \
            int e = l * 256 + tid, r = e >> 3, c = e & 7;                               \
            cpa16(SWC(sa, r, c), gA + (size_t)r * 1024 + c * 8);                        \
            cpa16(SWC(sb, r, c), gB + (size_t)r * 1024 + c * 8);                        \
        }                                                                               \
        cp_commit();                                                                    \
    };                                                                                  \
    load_chunk(0, 0);                                                                   \
    load_chunk(1, 1);                                                                   \
    const int rA0 = wm * 64 + (lane & 15);                                              \
    const int selA = lane >> 4;                                                         \
    const int cB0 = wn * 32 + (lane & 7) + ((lane >> 4) << 3);                          \
    const int selB = (lane >> 3) & 1;                                                   \
    uint32_t aRel[4], bRel[2];                                                          \
    _Pragma("unroll") for (int mi = 0; mi < 4; mi++) {                                  \
        const int r = rA0 + mi * 16;                                                    \
        aRel[mi] = r * 128 + ((selA ^ (r & 7)) << 4);                                   \
    }                                                                                   \
    _Pragma("unroll") for (int p = 0; p < 2; p++) {                                     \
        const int c = cB0 + p * 16;                                                     \
        bRel[p] = c * 128 + ((selB ^ (c & 7)) << 4);                                    \
    }                                                                                   \
    for (int kt = 0; kt < 16; kt++) {                                                   \
        if (kt < 15) cp_wait<1>(); else cp_wait<0>();                                   \
        __syncthreads();                                                                \
        const int s = kt % 3;                                                           \
        const uint32_t sa = smb + s * 32768;                                            \
        const uint32_t sb = sa + 16384;                                                 \
        _Pragma("unroll") for (int ks = 0; ks < 4; ks++) {                              \
            const uint32_t xk = ks << 5;                                                \
            uint32_t af[4][4], bf[4][2];                                                \
            _Pragma("unroll") for (int mi = 0; mi < 4; mi++)                            \
                ldsm4(af[mi][0], af[mi][1], af[mi][2], af[mi][3],                       \
                      (sa + aRel[mi]) ^ xk);                                            \
            _Pragma("unroll") for (int p = 0; p < 2; p++)                               \
                ldsm4(bf[2 * p][0], bf[2 * p][1], bf[2 * p + 1][0], bf[2 * p + 1][1],   \
                      (sb + bRel[p]) ^ xk);                                             \
            if (ks == 0 && kt < 14) load_chunk(kt + 2, (kt + 2) % 3);                   \
            _Pragma("unroll") for (int mi = 0; mi < 4; mi++)                            \
            _Pragma("unroll") for (int ni = 0; ni < 4; ni++)                            \
                mma16(acc[mi][ni], af[mi], bf[ni]);                                     \
        }                                                                               \
    }

// ---------------- Kernel 2: Q projection + attn epilogue (fp16 out) ----------------
__global__ void __launch_bounds__(256, 2) k_q_attn(
    const __half* __restrict__ A, const __half* __restrict__ WT,
    const float* __restrict__ BQ, const float* __restrict__ KV,
    const float* __restrict__ KS, __half* __restrict__ ATT)
{
    GEMM_MAIN(WT)
    const int b = rowBase >> 12;
    const int g = lane >> 2;
#pragma unroll
    for (int ni = 0; ni < 4; ni++) {
        const int c0 = colBase + wn * 32 + ni * 8 + 2 * (lane & 3);
        const float kv0 = KV[b * 1024 + c0], kv1 = KV[b * 1024 + c0 + 1];
        const float ks0 = KS[b * 1024 + c0], ks1 = KS[b * 1024 + c0 + 1];
        const float bq0 = BQ[c0], bq1 = BQ[c0 + 1];
#pragma unroll
        for (int mi = 0; mi < 4; mi++) {
            const int r0 = rowBase + wm * 64 + mi * 16 + g;
#pragma unroll
            for (int h = 0; h < 2; h++) {
                const int r = r0 + 8 * h;
                float Q0 = fmap(acc[mi][ni][2 * h + 0] + bq0);
                float Q1 = fmap(acc[mi][ni][2 * h + 1] + bq1);
                float a0 = __fdividef(Q0 * kv0, Q0 * ks0 + EPS);
                float a1 = __fdividef(Q1 * kv1, Q1 * ks1 + EPS);
                *(__half2*)(&ATT[(size_t)r * 1024 + c0]) = __floats2half2_rn(a0, a1);
            }
        }
    }
}

// ---------------- Kernel 3: output projection + gelu (fp32 out) ----------------
__global__ void __launch_bounds__(256, 2) k_out(
    const __half* __restrict__ A, const __half* __restrict__ WT,
    const float* __restrict__ BO, float* __restrict__ OUT)
{
    GEMM_MAIN(WT)
    const int g = lane >> 2;
#pragma unroll
    for (int ni = 0; ni < 4; ni++) {
        const int c0 = colBase + wn * 32 + ni * 8 + 2 * (lane & 3);
        const float bo0 = BO[c0], bo1 = BO[c0 + 1];
#pragma unroll
        for (int mi = 0; mi < 4; mi++) {
            const int r0 = rowBase + wm * 64 + mi * 16 + g;
#pragma unroll
            for (int h = 0; h < 2; h++) {
                const int r = r0 + 8 * h;
                float o0 = gelu_t(acc[mi][ni][2 * h + 0] + bo0);
                float o1 = gelu_t(acc[mi][ni][2 * h + 1] + bo1);
                *(float2*)(&OUT[(size_t)r * 1024 + c0]) = make_float2(o0, o1);
            }
        }
    }
}

// ---------------- host launcher ----------------
extern "C" void kernel_launch(void* const* d_in, const int* in_sizes, int n_in,
                              void* d_out, int out_size)
{
    const float* x  = (const float*)d_in[0];
    const float* wq = (const float*)d_in[1];
    const float* bq = (const float*)d_in[2];
    const float* wk = (const float*)d_in[3];
    const float* bk = (const float*)d_in[4];
    const float* wv = (const float*)d_in[5];
    const float* bv = (const float*)d_in[6];
    const float* wo = (const float*)d_in[7];
    const float* bo = (const float*)d_in[8];
    float* out = (float*)d_out;

    void *p_xh, *p_wq, *p_wk, *p_wv, *p_wo, *p_att, *p_kv, *p_ks;
    cudaGetSymbolAddress(&p_xh,  g_xh);
    cudaGetSymbolAddress(&p_wq,  g_wqT);
    cudaGetSymbolAddress(&p_wk,  g_wkT);
    cudaGetSymbolAddress(&p_wv,  g_wvT);
    cudaGetSymbolAddress(&p_wo,  g_woT);
    cudaGetSymbolAddress(&p_att, g_att);
    cudaGetSymbolAddress(&p_kv,  g_KV);
    cudaGetSymbolAddress(&p_ks,  g_KS);

    const int SMB = 98304 + 128;   // 3 stages x 32K + alignment slack
    cudaFuncSetAttribute(k_kv,     cudaFuncAttributeMaxDynamicSharedMemorySize, SMB);
    cudaFuncSetAttribute(k_q_attn, cudaFuncAttributeMaxDynamicSharedMemorySize, SMB);
    cudaFuncSetAttribute(k_out,    cudaFuncAttributeMaxDynamicSharedMemorySize, SMB);

    // prep: x -> fp16 (+ zero accumulators); transpose+convert weights to [N,K] fp16
    k_tohalf<<<32768, 256>>>((const float4*)x, (__half2*)p_xh, 8388608,
                             (float*)p_kv, (float*)p_ks);
    k_wt<<<dim3(32, 32, 4), dim3(32, 8)>>>(wq, (__half*)p_wq, wk, (__half*)p_wk,
                                           wv, (__half*)p_wv, wo, (__half*)p_wo);

    // 1) K,V projections + KV/Ksum reduction (K,V never materialized)
    k_kv<<<dim3(16, 256), 256, SMB>>>((const __half*)p_xh,
                                      (const __half*)p_wk, (const __half*)p_wv,
                                      bk, bv, (float*)p_kv, (float*)p_ks);
    // 2) Q projection + linear-attention epilogue -> attn scratch (fp16)
    k_q_attn<<<dim3(8, 256), 256, SMB>>>((const __half*)p_xh, (const __half*)p_wq, bq,
                                         (const float*)p_kv, (const float*)p_ks,
                                         (__half*)p_att);
    // 3) output projection + gelu
    k_out<<<dim3(8, 256), 256, SMB>>>((const __half*)p_att, (const __half*)p_wo, bo, out);
}

// round 16
// speedup vs baseline: 1.5561x; 1.0041x over previous
#include <cuda_runtime.h>
#include <cuda_fp16.h>
#include <cstdint>

#define EPS 1e-6f
// B=8, S=4096, IN=1024, HD=1024, OUT=1024, M=32768

// ---------------- scratch (allocation-free device globals) ----------------
__device__ __half g_xh [33554432];  // fp16 x            [32768,1024] (64MB)
__device__ __half g_wqT[1048576];   // [N,K] transposed fp16
__device__ __half g_wkT[1048576];
__device__ __half g_wvT[1048576];
__device__ __half g_woT[1048576];
__device__ __half g_att[33554432];  // attn scratch fp16 (64MB)
__device__ float  g_KV[8192];       // [B, H*D]
__device__ float  g_KS[8192];

// ---------------- helpers ----------------
__device__ __forceinline__ uint32_t sptr(const void* p) {
    return (uint32_t)__cvta_generic_to_shared(p);
}
__device__ __forceinline__ void cpa16(uint32_t d, const void* s) {
    asm volatile("cp.async.cg.shared.global [%0], [%1], 16;\n" :: "r"(d), "l"(s));
}
__device__ __forceinline__ void cp_commit() { asm volatile("cp.async.commit_group;\n"); }
template<int N> __device__ __forceinline__ void cp_wait() {
    asm volatile("cp.async.wait_group %0;\n" :: "n"(N));
}
__device__ __forceinline__ void ldsm4(uint32_t& r0, uint32_t& r1, uint32_t& r2, uint32_t& r3,
                                      uint32_t a) {
    asm volatile("ldmatrix.sync.aligned.m8n8.x4.shared.b16 {%0,%1,%2,%3}, [%4];"
                 : "=r"(r0), "=r"(r1), "=r"(r2), "=r"(r3) : "r"(a));
}
__device__ __forceinline__ void mma16(float* c, const uint32_t* a, const uint32_t* b) {
    asm volatile(
        "mma.sync.aligned.m16n8k16.row.col.f32.f16.f16.f32 "
        "{%0,%1,%2,%3}, {%4,%5,%6,%7}, {%8,%9}, {%0,%1,%2,%3};"
        : "+f"(c[0]), "+f"(c[1]), "+f"(c[2]), "+f"(c[3])
        : "r"(a[0]), "r"(a[1]), "r"(a[2]), "r"(a[3]), "r"(b[0]), "r"(b[1]));
}
__device__ __forceinline__ float fmap(float x) {   // elu(x)+1
    return x > 0.f ? x + 1.f : __expf(x);
}
// tanh-approx gelu via sigmoid identity: gelu(x) = x - x/(exp(2z)+1)
__device__ __forceinline__ float gelu_t(float x) {
    float z2 = 1.5957691216057308f * (x + 0.044715f * x * x * x);
    float e  = __expf(z2);
    return x - x * __fdividef(1.f, e + 1.f);
}

// ---------------- fused prep kernel ----------------
// blocks [0, 32768): x -> fp16 (first 32 also zero KV/KS)
// blocks [32768, 36864): weight transpose 1024x1024 [K][N]->[N][K] fp16 (4 matrices)
__global__ void k_prep(const float4* __restrict__ xsrc, __half2* __restrict__ xdst,
                       float* __restrict__ KV, float* __restrict__ KS,
                       const float* __restrict__ s0, __half* __restrict__ d0,
                       const float* __restrict__ s1, __half* __restrict__ d1,
                       const float* __restrict__ s2, __half* __restrict__ d2,
                       const float* __restrict__ s3, __half* __restrict__ d3)
{
    __shared__ float t[32][33];
    const int bid = blockIdx.x, tid = threadIdx.x;
    if (bid < 32768) {
        if (bid < 32) {
            int j = bid * 256 + tid;   // 8192 entries
            KV[j] = 0.f;
            KS[j] = 0.f;
        }
        int i = bid * 256 + tid;       // n4 = 8388608 = 32768*256 exactly
        float4 v = xsrc[i];
        xdst[2 * i]     = __floats2half2_rn(v.x, v.y);
        xdst[2 * i + 1] = __floats2half2_rn(v.z, v.w);
    } else {
        const int w = bid - 32768;             // 0..4095
        const int z = w >> 10, rem = w & 1023;
        const float* src; __half* dst;
        switch (z) {
            case 0:  src = s0; dst = d0; break;
            case 1:  src = s1; dst = d1; break;
            case 2:  src = s2; dst = d2; break;
            default: src = s3; dst = d3; break;
        }
        const int bx = (rem & 31) << 5, by = (rem >> 5) << 5;
        const int tx = tid & 31, ty = tid >> 5;   // 32 x 8
#pragma unroll
        for (int i = 0; i < 4; i++)
            t[ty + i * 8][tx] = src[(size_t)(by + ty + i * 8) * 1024 + bx + tx];
        __syncthreads();
#pragma unroll
        for (int i = 0; i < 4; i++)
            dst[(size_t)(bx + ty + i * 8) * 1024 + by + tx] = __float2half_rn(t[tx][ty + i * 8]);
    }
}

// swizzled smem byte address of 16B chunk (r row of 128B, c chunk 0..7)
#define SWC(base, r, c) ((base) + (r) * 128 + (((c) ^ ((r) & 7)) << 4))

// ---------------- Kernel 1: K/V dual-GEMM + KV/Ksum reduction ----------------
// BM=128, BN=64, BK=64, 256 thr, warps 4(m)x2(n), warp tile 32x32
// smem/stage: A 16K + Bk 8K + Bv 8K = 32K; 3 stages = 96K; 2 CTA/SM
__global__ void __launch_bounds__(256, 2) k_kv(
    const __half* __restrict__ X, const __half* __restrict__ WkT, const __half* __restrict__ WvT,
    const float* __restrict__ BK, const float* __restrict__ BV,
    float* __restrict__ KV, float* __restrict__ KS)
{
    extern __shared__ char sm[];
    const uint32_t smb = (sptr(sm) + 127u) & ~127u;   // 128B-aligned: XOR addressing valid
    const int tid = threadIdx.x, lane = tid & 31, wid = tid >> 5;
    const int wm = wid >> 1, wn = wid & 1;
    const int rowBase = blockIdx.y << 7;
    const int colBase = blockIdx.x << 6;

    float accK[2][4][4], accV[2][4][4];
#pragma unroll
    for (int i = 0; i < 2; i++)
#pragma unroll
        for (int j = 0; j < 4; j++)
#pragma unroll
            for (int c = 0; c < 4; c++) { accK[i][j][c] = 0.f; accV[i][j][c] = 0.f; }

    auto load_chunk = [&](int kt, int s) {
        const uint32_t sa  = smb + s * 32768;
        const uint32_t sbk = sa + 16384;
        const uint32_t sbv = sbk + 8192;
        const __half* gA = X   + (size_t)rowBase * 1024 + kt * 64;
        const __half* gK = WkT + (size_t)colBase * 1024 + kt * 64;
        const __half* gV = WvT + (size_t)colBase * 1024 + kt * 64;
#pragma unroll
        for (int l = 0; l < 4; l++) {
            int e = l * 256 + tid, r = e >> 3, c = e & 7;
            cpa16(SWC(sa, r, c), gA + (size_t)r * 1024 + c * 8);
        }
#pragma unroll
        for (int l = 0; l < 2; l++) {
            int e = l * 256 + tid, r = e >> 3, c = e & 7;
            cpa16(SWC(sbk, r, c), gK + (size_t)r * 1024 + c * 8);
            cpa16(SWC(sbv, r, c), gV + (size_t)r * 1024 + c * 8);
        }
        cp_commit();
    };

    load_chunk(0, 0);
    load_chunk(1, 1);

    // ldmatrix lane roles + precomputed swizzle-folded relative addresses
    const int rA0 = wm * 32 + (lane & 15);
    const int selA = lane >> 4;
    const int cB0 = wn * 32 + (lane & 7) + ((lane >> 4) << 3);
    const int selB = (lane >> 3) & 1;
    uint32_t aRel[2], bRel[2];
#pragma unroll
    for (int mi = 0; mi < 2; mi++) {
        const int r = rA0 + mi * 16;
        aRel[mi] = r * 128 + ((selA ^ (r & 7)) << 4);
    }
#pragma unroll
    for (int p = 0; p < 2; p++) {
        const int c = cB0 + p * 16;
        bRel[p] = c * 128 + ((selB ^ (c & 7)) << 4);
    }

    for (int kt = 0; kt < 16; kt++) {
        if (kt < 15) cp_wait<1>(); else cp_wait<0>();
        __syncthreads();
        const int s = kt % 3;
        const uint32_t sa  = smb + s * 32768;
        const uint32_t sbk = sa + 16384;
        const uint32_t sbv = sbk + 8192;
#pragma unroll
        for (int ks = 0; ks < 4; ks++) {
            const uint32_t xk = ks << 5;
            uint32_t af[2][4], bk2[4][2], bv2[4][2];
            // issue order: af[0], all B, af[1] -> first MMA waits on fewer loads
            ldsm4(af[0][0], af[0][1], af[0][2], af[0][3], (sa + aRel[0]) ^ xk);
#pragma unroll
            for (int p = 0; p < 2; p++) {
                const uint32_t off = bRel[p] ^ xk;
                ldsm4(bk2[2 * p][0], bk2[2 * p][1], bk2[2 * p + 1][0], bk2[2 * p + 1][1],
                      sbk + off);
                ldsm4(bv2[2 * p][0], bv2[2 * p][1], bv2[2 * p + 1][0], bv2[2 * p + 1][1],
                      sbv + off);
            }
            ldsm4(af[1][0], af[1][1], af[1][2], af[1][3], (sa + aRel[1]) ^ xk);
            // overlap next-chunk cp.async issue with LDSM latency
            if (ks == 0 && kt < 14) load_chunk(kt + 2, (kt + 2) % 3);
#pragma unroll
            for (int mi = 0; mi < 2; mi++)
#pragma unroll
                for (int ni = 0; ni < 4; ni++) {
                    mma16(accK[mi][ni], af[mi], bk2[ni]);
                    mma16(accV[mi][ni], af[mi], bv2[ni]);
                }
        }
    }

    // epilogue: K = elu+1, reduce K*v and K over the 128 s-rows of this block
    const int b = rowBase >> 12;
#pragma unroll
    for (int ni = 0; ni < 4; ni++) {
#pragma unroll
        for (int c = 0; c < 2; c++) {
            const int colg = colBase + wn * 32 + ni * 8 + 2 * (lane & 3) + c;
            const float bkc = BK[colg], bvc = BV[colg];
            float skv = 0.f, sk = 0.f;
#pragma unroll
            for (int mi = 0; mi < 2; mi++) {
                float kA = accK[mi][ni][c]     + bkc;
                float kB = accK[mi][ni][c + 2] + bkc;
                float vA = accV[mi][ni][c]     + bvc;
                float vB = accV[mi][ni][c + 2] + bvc;
                float KA = fmap(kA), KB = fmap(kB);
                skv += KA * vA + KB * vB;
                sk  += KA + KB;
            }
#pragma unroll
            for (int off = 16; off >= 4; off >>= 1) {
                skv += __shfl_xor_sync(0xffffffffu, skv, off);
                sk  += __shfl_xor_sync(0xffffffffu, sk,  off);
            }
            if (lane < 4) {
                atomicAdd(&KV[b * 1024 + colg], skv);
                atomicAdd(&KS[b * 1024 + colg], sk);
            }
        }
    }
}

// ---------------- Kernels 2/3 common mainloop ----------------
// BM=128, BN=128, BK=64, 256 thr, warps 2(m)x4(n), warp tile 64x32
// smem/stage: A 16K + B 16K = 32K; 3 stages = 96K; 2 CTA/SM
#define GEMM_MAIN(WT)                                                                   \
    extern __shared__ char sm[];                                                        \
    const uint32_t smb = (sptr(sm) + 127u) & ~127u;                                     \
    const int tid = threadIdx.x, lane = tid & 31, wid = tid >> 5;                       \
    const int wm = wid >> 2, wn = wid & 3;                                              \
    const int rowBase = blockIdx.y << 7;                                                \
    const int colBase = blockIdx.x << 7;                                                \
    float acc[4][4][4];                                                                 \
    _Pragma("unroll") for (int i = 0; i < 4; i++)                                       \
    _Pragma("unroll") for (int j = 0; j < 4; j++)                                       \
    _Pragma("unroll") for (int c = 0; c < 4; c++) acc[i][j][c] = 0.f;                   \
    auto load_chunk = [&](int kt, int s) {                                              \
        const uint32_t sa = smb + s * 32768;                                            \
        const uint32_t sb = sa + 16384;                                                 \
        const __half* gA = A  + (size_t)rowBase * 1024 + kt * 64;                       \
        const __half* gB = WT + (size_t)colBase * 1024 + kt * 64;                       \
        _Pragma("unroll") for (int l = 0; l < 4; l++) {                                 \
            int e = l * 256 + tid, r = e >> 3, c = e & 7;                               \
            cpa16(SWC(sa, r, c), gA + (size_t)r * 1024 + c * 8);                        \
            cpa16(SWC(sb, r, c), gB + (size_t)r * 1024 + c * 8);                        \
        }                                                                               \
        cp_commit();                                                                    \
    };                                                                                  \
    load_chunk(0, 0);                                                                   \
    load_chunk(1, 1);                                                                   \
    const int rA0 = wm * 64 + (lane & 15);                                              \
    const int selA = lane >> 4;                                                         \
    const int cB0 = wn * 32 + (lane & 7) + ((lane >> 4) << 3);                          \
    const int selB = (lane >> 3) & 1;                                                   \
    uint32_t aRel[4], bRel[2];                                                          \
    _Pragma("unroll") for (int mi = 0; mi < 4; mi++) {                                  \
        const int r = rA0 + mi * 16;                                                    \
        aRel[mi] = r * 128 + ((selA ^ (r & 7)) << 4);                                   \
    }                                                                                   \
    _Pragma("unroll") for (int p = 0; p < 2; p++) {                                     \
        const int c = cB0 + p * 16;                                                     \
        bRel[p] = c * 128 + ((selB ^ (c & 7)) << 4);                                    \
    }                                                                                   \
    for (int kt = 0; kt < 16; kt++) {                                                   \
        if (kt < 15) cp_wait<1>(); else cp_wait<0>();                                   \
        __syncthreads();                                                                \
        const int s = kt % 3;                                                           \
        const uint32_t sa = smb + s * 32768;                                            \
        const uint32_t sb = sa + 16384;                                                 \
        _Pragma("unroll") for (int ks = 0; ks < 4; ks++) {                              \
            const uint32_t xk = ks << 5;                                                \
            uint32_t af[4][4], bf[4][2];                                                \
            /* issue order: af[0], B pair, af[1..3] */                                  \
            ldsm4(af[0][0], af[0][1], af[0][2], af[0][3], (sa + aRel[0]) ^ xk);         \
            _Pragma("unroll") for (int p = 0; p < 2; p++)                               \
                ldsm4(bf[2 * p][0], bf[2 * p][1], bf[2 * p + 1][0], bf[2 * p + 1][1],   \
                      (sb + bRel[p]) ^ xk);                                             \
            _Pragma("unroll") for (int mi = 1; mi < 4; mi++)                            \
                ldsm4(af[mi][0], af[mi][1], af[mi][2], af[mi][3],                       \
                      (sa + aRel[mi]) ^ xk);                                            \
            if (ks == 0 && kt < 14) load_chunk(kt + 2, (kt + 2) % 3);                   \
            _Pragma("unroll") for (int mi = 0; mi < 4; mi++)                            \
            _Pragma("unroll") for (int ni = 0; ni < 4; ni++)                            \
                mma16(acc[mi][ni], af[mi], bf[ni]);                                     \
        }                                                                               \
    }

// ---------------- Kernel 2: Q projection + attn epilogue (fp16 out) ----------------
__global__ void __launch_bounds__(256, 2) k_q_attn(
    const __half* __restrict__ A, const __half* __restrict__ WT,
    const float* __restrict__ BQ, const float* __restrict__ KV,
    const float* __restrict__ KS, __half* __restrict__ ATT)
{
    GEMM_MAIN(WT)
    const int b = rowBase >> 12;
    const int g = lane >> 2;
#pragma unroll
    for (int ni = 0; ni < 4; ni++) {
        const int c0 = colBase + wn * 32 + ni * 8 + 2 * (lane & 3);
        const float kv0 = KV[b * 1024 + c0], kv1 = KV[b * 1024 + c0 + 1];
        const float ks0 = KS[b * 1024 + c0], ks1 = KS[b * 1024 + c0 + 1];
        const float bq0 = BQ[c0], bq1 = BQ[c0 + 1];
#pragma unroll
        for (int mi = 0; mi < 4; mi++) {
            const int r0 = rowBase + wm * 64 + mi * 16 + g;
#pragma unroll
            for (int h = 0; h < 2; h++) {
                const int r = r0 + 8 * h;
                float Q0 = fmap(acc[mi][ni][2 * h + 0] + bq0);
                float Q1 = fmap(acc[mi][ni][2 * h + 1] + bq1);
                float a0 = __fdividef(Q0 * kv0, Q0 * ks0 + EPS);
                float a1 = __fdividef(Q1 * kv1, Q1 * ks1 + EPS);
                *(__half2*)(&ATT[(size_t)r * 1024 + c0]) = __floats2half2_rn(a0, a1);
            }
        }
    }
}

// ---------------- Kernel 3: output projection + gelu (fp32 out) ----------------
__global__ void __launch_bounds__(256, 2) k_out(
    const __half* __restrict__ A, const __half* __restrict__ WT,
    const float* __restrict__ BO, float* __restrict__ OUT)
{
    GEMM_MAIN(WT)
    const int g = lane >> 2;
#pragma unroll
    for (int ni = 0; ni < 4; ni++) {
        const int c0 = colBase + wn * 32 + ni * 8 + 2 * (lane & 3);
        const float bo0 = BO[c0], bo1 = BO[c0 + 1];
#pragma unroll
        for (int mi = 0; mi < 4; mi++) {
            const int r0 = rowBase + wm * 64 + mi * 16 + g;
#pragma unroll
            for (int h = 0; h < 2; h++) {
                const int r = r0 + 8 * h;
                float o0 = gelu_t(acc[mi][ni][2 * h + 0] + bo0);
                float o1 = gelu_t(acc[mi][ni][2 * h + 1] + bo1);
                *(float2*)(&OUT[(size_t)r * 1024 + c0]) = make_float2(o0, o1);
            }
        }
    }
}

// ---------------- host launcher ----------------
extern "C" void kernel_launch(void* const* d_in, const int* in_sizes, int n_in,
                              void* d_out, int out_size)
{
    const float* x  = (const float*)d_in[0];
    const float* wq = (const float*)d_in[1];
    const float* bq = (const float*)d_in[2];
    const float* wk = (const float*)d_in[3];
    const float* bk = (const float*)d_in[4];
    const float* wv = (const float*)d_in[5];
    const float* bv = (const float*)d_in[6];
    const float* wo = (const float*)d_in[7];
    const float* bo = (const float*)d_in[8];
    float* out = (float*)d_out;

    void *p_xh, *p_wq, *p_wk, *p_wv, *p_wo, *p_att, *p_kv, *p_ks;
    cudaGetSymbolAddress(&p_xh,  g_xh);
    cudaGetSymbolAddress(&p_wq,  g_wqT);
    cudaGetSymbolAddress(&p_wk,  g_wkT);
    cudaGetSymbolAddress(&p_wv,  g_wvT);
    cudaGetSymbolAddress(&p_wo,  g_woT);
    cudaGetSymbolAddress(&p_att, g_att);
    cudaGetSymbolAddress(&p_kv,  g_KV);
    cudaGetSymbolAddress(&p_ks,  g_KS);

    const int SMB = 98304 + 128;   // 3 stages x 32K + alignment slack
    cudaFuncSetAttribute(k_kv,     cudaFuncAttributeMaxDynamicSharedMemorySize, SMB);
    cudaFuncSetAttribute(k_q_attn, cudaFuncAttributeMaxDynamicSharedMemorySize, SMB);
    cudaFuncSetAttribute(k_out,    cudaFuncAttributeMaxDynamicSharedMemorySize, SMB);

    // prep (single launch): x -> fp16 + KV/KS zero + 4 weight transposes
    k_prep<<<36864, 256>>>((const float4*)x, (__half2*)p_xh,
                           (float*)p_kv, (float*)p_ks,
                           wq, (__half*)p_wq, wk, (__half*)p_wk,
                           wv, (__half*)p_wv, wo, (__half*)p_wo);

    // 1) K,V projections + KV/Ksum reduction (K,V never materialized)
    k_kv<<<dim3(16, 256), 256, SMB>>>((const __half*)p_xh,
                                      (const __half*)p_wk, (const __half*)p_wv,
                                      bk, bv, (float*)p_kv, (float*)p_ks);
    // 2) Q projection + linear-attention epilogue -> attn scratch (fp16)
    k_q_attn<<<dim3(8, 256), 256, SMB>>>((const __half*)p_xh, (const __half*)p_wq, bq,
                                         (const float*)p_kv, (const float*)p_ks,
                                         (__half*)p_att);
    // 3) output projection + gelu
    k_out<<<dim3(8, 256), 256, SMB>>>((const __half*)p_att, (const __half*)p_wo, bo, out);
}

// round 17
// speedup vs baseline: 1.5653x; 1.0060x over previous
#include <cuda_runtime.h>
#include <cuda_fp16.h>
#include <cstdint>

#define EPS 1e-6f
// B=8, S=4096, IN=1024, HD=1024, OUT=1024, M=32768

// ---------------- scratch (allocation-free device globals) ----------------
__device__ __half g_xh [33554432];  // fp16 x            [32768,1024] (64MB)
__device__ __half g_wqT[1048576];   // [N,K] transposed fp16
__device__ __half g_wkT[1048576];
__device__ __half g_wvT[1048576];
__device__ __half g_woT[1048576];
__device__ __half g_att[33554432];  // attn scratch fp16 (64MB)
__device__ float  g_KV[8192];       // [B, H*D]
__device__ float  g_KS[8192];

// ---------------- helpers ----------------
__device__ __forceinline__ uint32_t sptr(const void* p) {
    return (uint32_t)__cvta_generic_to_shared(p);
}
__device__ __forceinline__ void cpa16(uint32_t d, const void* s) {
    asm volatile("cp.async.cg.shared.global [%0], [%1], 16;\n" :: "r"(d), "l"(s));
}
__device__ __forceinline__ void cp_commit() { asm volatile("cp.async.commit_group;\n"); }
template<int N> __device__ __forceinline__ void cp_wait() {
    asm volatile("cp.async.wait_group %0;\n" :: "n"(N));
}
__device__ __forceinline__ void ldsm4(uint32_t& r0, uint32_t& r1, uint32_t& r2, uint32_t& r3,
                                      uint32_t a) {
    asm volatile("ldmatrix.sync.aligned.m8n8.x4.shared.b16 {%0,%1,%2,%3}, [%4];"
                 : "=r"(r0), "=r"(r1), "=r"(r2), "=r"(r3) : "r"(a));
}
__device__ __forceinline__ void mma16(float* c, const uint32_t* a, const uint32_t* b) {
    asm volatile(
        "mma.sync.aligned.m16n8k16.row.col.f32.f16.f16.f32 "
        "{%0,%1,%2,%3}, {%4,%5,%6,%7}, {%8,%9}, {%0,%1,%2,%3};"
        : "+f"(c[0]), "+f"(c[1]), "+f"(c[2]), "+f"(c[3])
        : "r"(a[0]), "r"(a[1]), "r"(a[2]), "r"(a[3]), "r"(b[0]), "r"(b[1]));
}
__device__ __forceinline__ float fmap(float x) {   // elu(x)+1
    return x > 0.f ? x + 1.f : __expf(x);
}
// tanh-approx gelu via sigmoid identity: gelu(x) = x - x/(exp(2z)+1)
__device__ __forceinline__ float gelu_t(float x) {
    float z2 = 1.5957691216057308f * (x + 0.044715f * x * x * x);
    float e  = __expf(z2);
    return x - x * __fdividef(1.f, e + 1.f);
}

// ---------------- fused prep kernel ----------------
// blocks [0, 32768): x -> fp16 (first 32 also zero KV/KS)
// blocks [32768, 36864): weight transpose 1024x1024 [K][N]->[N][K] fp16 (4 matrices)
__global__ void k_prep(const float4* __restrict__ xsrc, __half2* __restrict__ xdst,
                       float* __restrict__ KV, float* __restrict__ KS,
                       const float* __restrict__ s0, __half* __restrict__ d0,
                       const float* __restrict__ s1, __half* __restrict__ d1,
                       const float* __restrict__ s2, __half* __restrict__ d2,
                       const float* __restrict__ s3, __half* __restrict__ d3)
{
    __shared__ float t[32][33];
    const int bid = blockIdx.x, tid = threadIdx.x;
    if (bid < 32768) {
        if (bid < 32) {
            int j = bid * 256 + tid;   // 8192 entries
            KV[j] = 0.f;
            KS[j] = 0.f;
        }
        int i = bid * 256 + tid;       // n4 = 8388608 = 32768*256 exactly
        float4 v = __ldcs(&xsrc[i]);   // fp32 x read exactly once: don't pollute L2
        xdst[2 * i]     = __floats2half2_rn(v.x, v.y);
        xdst[2 * i + 1] = __floats2half2_rn(v.z, v.w);
    } else {
        const int w = bid - 32768;             // 0..4095
        const int z = w >> 10, rem = w & 1023;
        const float* src; __half* dst;
        switch (z) {
            case 0:  src = s0; dst = d0; break;
            case 1:  src = s1; dst = d1; break;
            case 2:  src = s2; dst = d2; break;
            default: src = s3; dst = d3; break;
        }
        const int bx = (rem & 31) << 5, by = (rem >> 5) << 5;
        const int tx = tid & 31, ty = tid >> 5;   // 32 x 8
#pragma unroll
        for (int i = 0; i < 4; i++)
            t[ty + i * 8][tx] = src[(size_t)(by + ty + i * 8) * 1024 + bx + tx];
        __syncthreads();
#pragma unroll
        for (int i = 0; i < 4; i++)
            dst[(size_t)(bx + ty + i * 8) * 1024 + by + tx] = __float2half_rn(t[tx][ty + i * 8]);
    }
}

// swizzled smem byte address of 16B chunk (r row of 128B, c chunk 0..7)
#define SWC(base, r, c) ((base) + (r) * 128 + (((c) ^ ((r) & 7)) << 4))

// ---------------- Kernel 1: K/V dual-GEMM + KV/Ksum reduction ----------------
// BM=128, BN=64, BK=64, 256 thr, warps 4(m)x2(n), warp tile 32x32
// smem/stage: A 16K + Bk 8K + Bv 8K = 32K; 3 stages = 96K; 2 CTA/SM
__global__ void __launch_bounds__(256, 2) k_kv(
    const __half* __restrict__ X, const __half* __restrict__ WkT, const __half* __restrict__ WvT,
    const float* __restrict__ BK, const float* __restrict__ BV,
    float* __restrict__ KV, float* __restrict__ KS)
{
    extern __shared__ char sm[];
    const uint32_t smb = (sptr(sm) + 127u) & ~127u;   // 128B-aligned: XOR addressing valid
    const int tid = threadIdx.x, lane = tid & 31, wid = tid >> 5;
    const int wm = wid >> 1, wn = wid & 1;
    const int rowBase = blockIdx.y << 7;
    const int colBase = blockIdx.x << 6;

    float accK[2][4][4], accV[2][4][4];
#pragma unroll
    for (int i = 0; i < 2; i++)
#pragma unroll
        for (int j = 0; j < 4; j++)
#pragma unroll
            for (int c = 0; c < 4; c++) { accK[i][j][c] = 0.f; accV[i][j][c] = 0.f; }

    auto load_chunk = [&](int kt, int s) {
        const uint32_t sa  = smb + s * 32768;
        const uint32_t sbk = sa + 16384;
        const uint32_t sbv = sbk + 8192;
        const __half* gA = X   + (size_t)rowBase * 1024 + kt * 64;
        const __half* gK = WkT + (size_t)colBase * 1024 + kt * 64;
        const __half* gV = WvT + (size_t)colBase * 1024 + kt * 64;
#pragma unroll
        for (int l = 0; l < 4; l++) {
            int e = l * 256 + tid, r = e >> 3, c = e & 7;
            cpa16(SWC(sa, r, c), gA + (size_t)r * 1024 + c * 8);
        }
#pragma unroll
        for (int l = 0; l < 2; l++) {
            int e = l * 256 + tid, r = e >> 3, c = e & 7;
            cpa16(SWC(sbk, r, c), gK + (size_t)r * 1024 + c * 8);
            cpa16(SWC(sbv, r, c), gV + (size_t)r * 1024 + c * 8);
        }
        cp_commit();
    };

    load_chunk(0, 0);
    load_chunk(1, 1);

    // ldmatrix lane roles + precomputed swizzle-folded relative addresses
    const int rA0 = wm * 32 + (lane & 15);
    const int selA = lane >> 4;
    const int cB0 = wn * 32 + (lane & 7) + ((lane >> 4) << 3);
    const int selB = (lane >> 3) & 1;
    uint32_t aRel[2], bRel[2];
#pragma unroll
    for (int mi = 0; mi < 2; mi++) {
        const int r = rA0 + mi * 16;
        aRel[mi] = r * 128 + ((selA ^ (r & 7)) << 4);
    }
#pragma unroll
    for (int p = 0; p < 2; p++) {
        const int c = cB0 + p * 16;
        bRel[p] = c * 128 + ((selB ^ (c & 7)) << 4);
    }

    for (int kt = 0; kt < 16; kt++) {
        if (kt < 15) cp_wait<1>(); else cp_wait<0>();
        __syncthreads();
        const int s = kt % 3;
        const uint32_t sa  = smb + s * 32768;
        const uint32_t sbk = sa + 16384;
        const uint32_t sbv = sbk + 8192;
#pragma unroll
        for (int ks = 0; ks < 4; ks++) {
            const uint32_t xk = ks << 5;
            uint32_t af[2][4], bk2[4][2], bv2[4][2];
            // issue order: af[0], all B, af[1] -> first MMA waits on fewer loads
            ldsm4(af[0][0], af[0][1], af[0][2], af[0][3], (sa + aRel[0]) ^ xk);
#pragma unroll
            for (int p = 0; p < 2; p++) {
                const uint32_t off = bRel[p] ^ xk;
                ldsm4(bk2[2 * p][0], bk2[2 * p][1], bk2[2 * p + 1][0], bk2[2 * p + 1][1],
                      sbk + off);
                ldsm4(bv2[2 * p][0], bv2[2 * p][1], bv2[2 * p + 1][0], bv2[2 * p + 1][1],
                      sbv + off);
            }
            ldsm4(af[1][0], af[1][1], af[1][2], af[1][3], (sa + aRel[1]) ^ xk);
            // overlap next-chunk cp.async issue with LDSM latency
            if (ks == 0 && kt < 14) load_chunk(kt + 2, (kt + 2) % 3);
#pragma unroll
            for (int mi = 0; mi < 2; mi++)
#pragma unroll
                for (int ni = 0; ni < 4; ni++) {
                    mma16(accK[mi][ni], af[mi], bk2[ni]);
                    mma16(accV[mi][ni], af[mi], bv2[ni]);
                }
        }
    }

    // epilogue: K = elu+1, reduce K*v and K over the 128 s-rows of this block
    const int b = rowBase >> 12;
#pragma unroll
    for (int ni = 0; ni < 4; ni++) {
#pragma unroll
        for (int c = 0; c < 2; c++) {
            const int colg = colBase + wn * 32 + ni * 8 + 2 * (lane & 3) + c;
            const float bkc = BK[colg], bvc = BV[colg];
            float skv = 0.f, sk = 0.f;
#pragma unroll
            for (int mi = 0; mi < 2; mi++) {
                float kA = accK[mi][ni][c]     + bkc;
                float kB = accK[mi][ni][c + 2] + bkc;
                float vA = accV[mi][ni][c]     + bvc;
                float vB = accV[mi][ni][c + 2] + bvc;
                float KA = fmap(kA), KB = fmap(kB);
                skv += KA * vA + KB * vB;
                sk  += KA + KB;
            }
#pragma unroll
            for (int off = 16; off >= 4; off >>= 1) {
                skv += __shfl_xor_sync(0xffffffffu, skv, off);
                sk  += __shfl_xor_sync(0xffffffffu, sk,  off);
            }
            if (lane < 4) {
                atomicAdd(&KV[b * 1024 + colg], skv);
                atomicAdd(&KS[b * 1024 + colg], sk);
            }
        }
    }
}

// ---------------- Kernels 2/3 common mainloop ----------------
// BM=128, BN=128, BK=64, 256 thr, warps 2(m)x4(n), warp tile 64x32
// smem/stage: A 16K + B 16K = 32K; 3 stages = 96K; 2 CTA/SM
#define GEMM_MAIN(WT)                                                                   \
    extern __shared__ char sm[];                                                        \
    const uint32_t smb = (sptr(sm) + 127u) & ~127u;                                     \
    const int tid = threadIdx.x, lane = tid & 31, wid = tid >> 5;                       \
    const int wm = wid >> 2, wn = wid & 3;                                              \
    const int rowBase = blockIdx.y << 7;                                                \
    const int colBase = blockIdx.x << 7;                                                \
    float acc[4][4][4];                                                                 \
    _Pragma("unroll") for (int i = 0; i < 4; i++)                                       \
    _Pragma("unroll") for (int j = 0; j < 4; j++)                                       \
    _Pragma("unroll") for (int c = 0; c < 4; c++) acc[i][j][c] = 0.f;                   \
    auto load_chunk = [&](int kt, int s) {                                              \
        const uint32_t sa = smb + s * 32768;                                            \
        const uint32_t sb = sa + 16384;                                                 \
        const __half* gA = A  + (size_t)rowBase * 1024 + kt * 64;                       \
        const __half* gB = WT + (size_t)colBase * 1024 + kt * 64;                       \
        _Pragma("unroll") for (int l = 0; l < 4; l++) {                                 \
            int e = l * 256 + tid, r = e >> 3, c = e & 7;                               \
            cpa16(SWC(sa, r, c), gA + (size_t)r * 1024 + c * 8);                        \
            cpa16(SWC(sb, r, c), gB + (size_t)r * 1024 + c * 8);                        \
        }                                                                               \
        cp_commit();                                                                    \
    };                                                                                  \
    load_chunk(0, 0);                                                                   \
    load_chunk(1, 1);                                                                   \
    const int rA0 = wm * 64 + (lane & 15);                                              \
    const int selA = lane >> 4;                                                         \
    const int cB0 = wn * 32 + (lane & 7) + ((lane >> 4) << 3);                          \
    const int selB = (lane >> 3) & 1;                                                   \
    uint32_t aRel[4], bRel[2];                                                          \
    _Pragma("unroll") for (int mi = 0; mi < 4; mi++) {                                  \
        const int r = rA0 + mi * 16;                                                    \
        aRel[mi] = r * 128 + ((selA ^ (r & 7)) << 4);                                   \
    }                                                                                   \
    _Pragma("unroll") for (int p = 0; p < 2; p++) {                                     \
        const int c = cB0 + p * 16;                                                     \
        bRel[p] = c * 128 + ((selB ^ (c & 7)) << 4);                                    \
    }                                                                                   \
    for (int kt = 0; kt < 16; kt++) {                                                   \
        if (kt < 15) cp_wait<1>(); else cp_wait<0>();                                   \
        __syncthreads();                                                                \
        const int s = kt % 3;                                                           \
        const uint32_t sa = smb + s * 32768;                                            \
        const uint32_t sb = sa + 16384;                                                 \
        _Pragma("unroll") for (int ks = 0; ks < 4; ks++) {                              \
            const uint32_t xk = ks << 5;                                                \
            uint32_t af[4][4], bf[4][2];                                                \
            /* issue order: af[0], B pair, af[1..3] */                                  \
            ldsm4(af[0][0], af[0][1], af[0][2], af[0][3], (sa + aRel[0]) ^ xk);         \
            _Pragma("unroll") for (int p = 0; p < 2; p++)                               \
                ldsm4(bf[2 * p][0], bf[2 * p][1], bf[2 * p + 1][0], bf[2 * p + 1][1],   \
                      (sb + bRel[p]) ^ xk);                                             \
            _Pragma("unroll") for (int mi = 1; mi < 4; mi++)                            \
                ldsm4(af[mi][0], af[mi][1], af[mi][2], af[mi][3],                       \
                      (sa + aRel[mi]) ^ xk);                                            \
            if (ks == 0 && kt < 14) load_chunk(kt + 2, (kt + 2) % 3);                   \
            _Pragma("unroll") for (int mi = 0; mi < 4; mi++)                            \
            _Pragma("unroll") for (int ni = 0; ni < 4; ni++)                            \
                mma16(acc[mi][ni], af[mi], bf[ni]);                                     \
        }                                                                               \
    }

// ---------------- Kernel 2: Q projection + attn epilogue (fp16 out) ----------------
__global__ void __launch_bounds__(256, 2) k_q_attn(
    const __half* __restrict__ A, const __half* __restrict__ WT,
    const float* __restrict__ BQ, const float* __restrict__ KV,
    const float* __restrict__ KS, __half* __restrict__ ATT)
{
    GEMM_MAIN(WT)
    const int b = rowBase >> 12;
    const int g = lane >> 2;
#pragma unroll
    for (int ni = 0; ni < 4; ni++) {
        const int c0 = colBase + wn * 32 + ni * 8 + 2 * (lane & 3);
        const float kv0 = KV[b * 1024 + c0], kv1 = KV[b * 1024 + c0 + 1];
        const float ks0 = KS[b * 1024 + c0], ks1 = KS[b * 1024 + c0 + 1];
        const float bq0 = BQ[c0], bq1 = BQ[c0 + 1];
#pragma unroll
        for (int mi = 0; mi < 4; mi++) {
            const int r0 = rowBase + wm * 64 + mi * 16 + g;
#pragma unroll
            for (int h = 0; h < 2; h++) {
                const int r = r0 + 8 * h;
                float Q0 = fmap(acc[mi][ni][2 * h + 0] + bq0);
                float Q1 = fmap(acc[mi][ni][2 * h + 1] + bq1);
                float a0 = __fdividef(Q0 * kv0, Q0 * ks0 + EPS);
                float a1 = __fdividef(Q1 * kv1, Q1 * ks1 + EPS);
                *(__half2*)(&ATT[(size_t)r * 1024 + c0]) = __floats2half2_rn(a0, a1);
            }
        }
    }
}

// ---------------- Kernel 3: output projection + gelu (fp32 out) ----------------
__global__ void __launch_bounds__(256, 2) k_out(
    const __half* __restrict__ A, const __half* __restrict__ WT,
    const float* __restrict__ BO, float* __restrict__ OUT)
{
    GEMM_MAIN(WT)
    const int g = lane >> 2;
#pragma unroll
    for (int ni = 0; ni < 4; ni++) {
        const int c0 = colBase + wn * 32 + ni * 8 + 2 * (lane & 3);
        const float bo0 = BO[c0], bo1 = BO[c0 + 1];
#pragma unroll
        for (int mi = 0; mi < 4; mi++) {
            const int r0 = rowBase + wm * 64 + mi * 16 + g;
#pragma unroll
            for (int h = 0; h < 2; h++) {
                const int r = r0 + 8 * h;
                float o0 = gelu_t(acc[mi][ni][2 * h + 0] + bo0);
                float o1 = gelu_t(acc[mi][ni][2 * h + 1] + bo1);
                // streaming store: OUT is never re-read; don't evict attn from L2
                __stcs((float2*)&OUT[(size_t)r * 1024 + c0], make_float2(o0, o1));
            }
        }
    }
}

// ---------------- host launcher ----------------
extern "C" void kernel_launch(void* const* d_in, const int* in_sizes, int n_in,
                              void* d_out, int out_size)
{
    const float* x  = (const float*)d_in[0];
    const float* wq = (const float*)d_in[1];
    const float* bq = (const float*)d_in[2];
    const float* wk = (const float*)d_in[3];
    const float* bk = (const float*)d_in[4];
    const float* wv = (const float*)d_in[5];
    const float* bv = (const float*)d_in[6];
    const float* wo = (const float*)d_in[7];
    const float* bo = (const float*)d_in[8];
    float* out = (float*)d_out;

    void *p_xh, *p_wq, *p_wk, *p_wv, *p_wo, *p_att, *p_kv, *p_ks;
    cudaGetSymbolAddress(&p_xh,  g_xh);
    cudaGetSymbolAddress(&p_wq,  g_wqT);
    cudaGetSymbolAddress(&p_wk,  g_wkT);
    cudaGetSymbolAddress(&p_wv,  g_wvT);
    cudaGetSymbolAddress(&p_wo,  g_woT);
    cudaGetSymbolAddress(&p_att, g_att);
    cudaGetSymbolAddress(&p_kv,  g_KV);
    cudaGetSymbolAddress(&p_ks,  g_KS);

    const int SMB = 98304 + 128;   // 3 stages x 32K + alignment slack
    cudaFuncSetAttribute(k_kv,     cudaFuncAttributeMaxDynamicSharedMemorySize, SMB);
    cudaFuncSetAttribute(k_q_attn, cudaFuncAttributeMaxDynamicSharedMemorySize, SMB);
    cudaFuncSetAttribute(k_out,    cudaFuncAttributeMaxDynamicSharedMemorySize, SMB);

    // prep (single launch): x -> fp16 + KV/KS zero + 4 weight transposes
    k_prep<<<36864, 256>>>((const float4*)x, (__half2*)p_xh,
                           (float*)p_kv, (float*)p_ks,
                           wq, (__half*)p_wq, wk, (__half*)p_wk,
                           wv, (__half*)p_wv, wo, (__half*)p_wo);

    // 1) K,V projections + KV/Ksum reduction (K,V never materialized)
    k_kv<<<dim3(16, 256), 256, SMB>>>((const __half*)p_xh,
                                      (const __half*)p_wk, (const __half*)p_wv,
                                      bk, bv, (float*)p_kv, (float*)p_ks);
    // 2) Q projection + linear-attention epilogue -> attn scratch (fp16)
    k_q_attn<<<dim3(8, 256), 256, SMB>>>((const __half*)p_xh, (const __half*)p_wq, bq,
                                         (const float*)p_kv, (const float*)p_ks,
                                         (__half*)p_att);
    // 3) output projection + gelu
    k_out<<<dim3(8, 256), 256, SMB>>>((const __half*)p_att, (const __half*)p_wo, bo, out);
}